// round 1
// baseline (speedup 1.0000x reference)
#include <cuda_runtime.h>
#include <math.h>

#define B_ 2
#define S_ 1024
#define HID_ 4096
#define NH_ 32
#define NKV_ 8
#define D_ 128
#define WINDOW_ 512
#define QKV_OUT_ ((NH_ + 2 * NKV_) * D_)   /* 6144 */
#define BS_ (B_ * S_)                      /* 2048 */
#define PADQ 68

/* ------------------------- scratch (static device globals) ---------------- */
__device__ float g_qkv[BS_ * QKV_OUT_];            /* 48 MB  raw qkv         */
__device__ float g_q[B_ * NH_ * S_ * D_];          /* 32 MB  rope'd q [b,h,s,d] */
__device__ float g_k[B_ * NKV_ * S_ * D_];         /* 8 MB   rope'd k [b,kv,s,d]*/
__device__ float g_v[B_ * NKV_ * S_ * D_];         /* 8 MB   v        [b,kv,s,d]*/
__device__ float g_attn[BS_ * (NH_ * D_)];         /* 32 MB  attn out [bs, h*D] */

/* ------------------------- generic SGEMM: C = A * Bt^T + bias ------------- */
/* A: [M,K] row-major.  Bt: [N,K] row-major.  C: [M,N].  M%128==N%128==K%8==0 */
__global__ void __launch_bounds__(256) sgemm_bias(
    const float* __restrict__ A, const float* __restrict__ Bt,
    const float* __restrict__ bias, float* __restrict__ C,
    int M, int N, int K)
{
    __shared__ float As[8][128];
    __shared__ float Bs[8][128];

    const int bm  = blockIdx.y * 128;
    const int bn  = blockIdx.x * 128;
    const int tid = threadIdx.x;
    const int lrow = tid >> 1;
    const int lk   = (tid & 1) * 4;
    const float* Ag = A  + (size_t)(bm + lrow) * K + lk;
    const float* Bg = Bt + (size_t)(bn + lrow) * K + lk;
    const int ty = tid >> 4, tx = tid & 15;

    float acc[8][8];
#pragma unroll
    for (int i = 0; i < 8; i++)
#pragma unroll
        for (int j = 0; j < 8; j++) acc[i][j] = 0.f;

    for (int k0 = 0; k0 < K; k0 += 8) {
        float4 av = *(const float4*)(Ag + k0);
        float4 bv = *(const float4*)(Bg + k0);
        __syncthreads();
        As[lk + 0][lrow] = av.x; As[lk + 1][lrow] = av.y;
        As[lk + 2][lrow] = av.z; As[lk + 3][lrow] = av.w;
        Bs[lk + 0][lrow] = bv.x; Bs[lk + 1][lrow] = bv.y;
        Bs[lk + 2][lrow] = bv.z; Bs[lk + 3][lrow] = bv.w;
        __syncthreads();
#pragma unroll
        for (int kk = 0; kk < 8; kk++) {
            float a[8], bb[8];
            *(float4*)&a[0]  = *(const float4*)&As[kk][ty * 8];
            *(float4*)&a[4]  = *(const float4*)&As[kk][ty * 8 + 4];
            *(float4*)&bb[0] = *(const float4*)&Bs[kk][tx * 8];
            *(float4*)&bb[4] = *(const float4*)&Bs[kk][tx * 8 + 4];
#pragma unroll
            for (int i = 0; i < 8; i++)
#pragma unroll
                for (int j = 0; j < 8; j++)
                    acc[i][j] = fmaf(a[i], bb[j], acc[i][j]);
        }
    }

#pragma unroll
    for (int i = 0; i < 8; i++) {
        int row = bm + ty * 8 + i;
        float* Cp = C + (size_t)row * N + bn + tx * 8;
        const float* bp = bias + bn + tx * 8;
        float4 o0, o1;
        o0.x = acc[i][0] + bp[0]; o0.y = acc[i][1] + bp[1];
        o0.z = acc[i][2] + bp[2]; o0.w = acc[i][3] + bp[3];
        o1.x = acc[i][4] + bp[4]; o1.y = acc[i][5] + bp[5];
        o1.z = acc[i][6] + bp[6]; o1.w = acc[i][7] + bp[7];
        *(float4*)Cp       = o0;
        *(float4*)(Cp + 4) = o1;
    }
}

/* ---------------- RoPE + split qkv into attention-friendly layouts -------- */
__global__ void rope_split_kernel(const float* __restrict__ cosp,
                                  const float* __restrict__ sinp)
{
    int idx = blockIdx.x * blockDim.x + threadIdx.x;
    if (idx >= BS_ * QKV_OUT_) return;
    int col = idx % QKV_OUT_;
    int bs  = idx / QKV_OUT_;
    int b   = bs / S_;
    int s   = bs - b * S_;
    int d   = col & (D_ - 1);
    float v = g_qkv[idx];

    if (col < NH_ * D_) {
        int h = col >> 7;
        float c  = cosp[s * D_ + d];
        float sn = sinp[s * D_ + d];
        float partner = g_qkv[(size_t)bs * QKV_OUT_ + (col ^ 64)];
        float r = (d < 64) ? -partner : partner;
        g_q[(((size_t)b * NH_ + h) * S_ + s) * D_ + d] = v * c + r * sn;
    } else if (col < (NH_ + NKV_) * D_) {
        int kvh = (col - NH_ * D_) >> 7;
        float c  = cosp[s * D_ + d];
        float sn = sinp[s * D_ + d];
        float partner = g_qkv[(size_t)bs * QKV_OUT_ + (col ^ 64)];
        float r = (d < 64) ? -partner : partner;
        g_k[(((size_t)b * NKV_ + kvh) * S_ + s) * D_ + d] = v * c + r * sn;
    } else {
        int kvh = (col - (NH_ + NKV_) * D_) >> 7;
        g_v[(((size_t)b * NKV_ + kvh) * S_ + s) * D_ + d] = v;
    }
}

/* -------- flash attention, sliding window 512, GQA (4 q heads / kv) ------- */
/* grid: (S/64, NH, B); 256 threads; dynamic smem ~118 KB                     */
__global__ void __launch_bounds__(256) attn_kernel()
{
    const int qb  = blockIdx.x;
    const int h   = blockIdx.y;
    const int b   = blockIdx.z;
    const int kvh = h >> 2;

    extern __shared__ float sm[];
    float* Qs     = sm;                    /* [128][PADQ]  Q^T (d-major), pre-scaled */
    float* Ks     = Qs + 128 * PADQ;       /* [128][PADQ]  K^T (d-major)            */
    float* Ps     = Ks + 128 * PADQ;       /* [64][PADQ]   P^T (key-major)          */
    float* Vs     = Ps + 64 * PADQ;        /* [64][128]                              */
    float* m_arr  = Vs + 64 * 128;
    float* l_arr  = m_arr + 64;
    float* sc_arr = l_arr + 64;

    const int tid = threadIdx.x;
    const int ty  = tid >> 4, tx = tid & 15;
    const int qlo = qb * 64;
    const float SCALE = 0.08838834764831845f;   /* 1/sqrt(128) */

    const float* Qg = g_q + (((size_t)b * NH_ + h) * S_ + qlo) * D_;
    for (int e = tid * 4; e < 64 * 128; e += 1024) {
        int q = e >> 7, d = e & 127;
        float4 v = *(const float4*)(Qg + e);
        Qs[(d + 0) * PADQ + q] = v.x * SCALE;
        Qs[(d + 1) * PADQ + q] = v.y * SCALE;
        Qs[(d + 2) * PADQ + q] = v.z * SCALE;
        Qs[(d + 3) * PADQ + q] = v.w * SCALE;
    }
    if (tid < 64) { m_arr[tid] = -1e30f; l_arr[tid] = 0.f; }

    float o[4][8];
#pragma unroll
    for (int i = 0; i < 4; i++)
#pragma unroll
        for (int c = 0; c < 8; c++) o[i][c] = 0.f;

    int ks = qlo - (WINDOW_ - 1);
    if (ks < 0) ks = 0;
    const int kb0 = ks >> 6, kb1 = qb;

    const float* Kg = g_k + (((size_t)b * NKV_ + kvh) * S_) * D_;
    const float* Vg = g_v + (((size_t)b * NKV_ + kvh) * S_) * D_;

    for (int kb = kb0; kb <= kb1; kb++) {
        __syncthreads();   /* prev iter done with Ps/Vs; first iter: Q loaded */
        const int kbase = kb * 64;
        for (int e = tid * 4; e < 64 * 128; e += 1024) {
            int r = e >> 7, d = e & 127;
            float4 kv4 = *(const float4*)(Kg + (size_t)kbase * D_ + e);
            Ks[(d + 0) * PADQ + r] = kv4.x;
            Ks[(d + 1) * PADQ + r] = kv4.y;
            Ks[(d + 2) * PADQ + r] = kv4.z;
            Ks[(d + 3) * PADQ + r] = kv4.w;
            float4 vv4 = *(const float4*)(Vg + (size_t)kbase * D_ + e);
            *(float4*)&Vs[r * 128 + d] = vv4;
        }
        __syncthreads();

        /* S = Q K^T (scaled) : each thread 4x4 of the 64x64 tile */
        float sacc[4][4];
#pragma unroll
        for (int i = 0; i < 4; i++)
#pragma unroll
            for (int j = 0; j < 4; j++) sacc[i][j] = 0.f;

#pragma unroll 8
        for (int kk = 0; kk < 128; kk++) {
            float qr[4], kr[4];
            *(float4*)qr = *(const float4*)&Qs[kk * PADQ + ty * 4];
            *(float4*)kr = *(const float4*)&Ks[kk * PADQ + tx * 4];
#pragma unroll
            for (int i = 0; i < 4; i++)
#pragma unroll
                for (int j = 0; j < 4; j++)
                    sacc[i][j] = fmaf(qr[i], kr[j], sacc[i][j]);
        }

        /* mask + store transposed */
#pragma unroll
        for (int j = 0; j < 4; j++) {
            int kg = kbase + tx * 4 + j;
#pragma unroll
            for (int i = 0; i < 4; i++) {
                int qg = qlo + ty * 4 + i;
                bool ok = (kg <= qg) && (qg - kg < WINDOW_);
                Ps[(tx * 4 + j) * PADQ + ty * 4 + i] = ok ? sacc[i][j] : -1e30f;
            }
        }
        __syncthreads();

        /* online softmax: one thread per query row */
        if (tid < 64) {
            const int q = tid;
            float mo = m_arr[q];
            float mx = mo;
#pragma unroll 8
            for (int k = 0; k < 64; k++) mx = fmaxf(mx, Ps[k * PADQ + q]);
            float l_add = 0.f;
#pragma unroll 4
            for (int k = 0; k < 64; k++) {
                float sv = Ps[k * PADQ + q];
                float p  = (sv > -1e29f) ? __expf(sv - mx) : 0.f;
                Ps[k * PADQ + q] = p;
                l_add += p;
            }
            float sf = __expf(mo - mx);
            l_arr[q]  = l_arr[q] * sf + l_add;
            m_arr[q]  = mx;
            sc_arr[q] = sf;
        }
        __syncthreads();

        /* rescale O, then O += P V */
        float sf[4];
#pragma unroll
        for (int i = 0; i < 4; i++) sf[i] = sc_arr[ty * 4 + i];
#pragma unroll
        for (int i = 0; i < 4; i++)
#pragma unroll
            for (int c = 0; c < 8; c++) o[i][c] *= sf[i];

#pragma unroll 8
        for (int kk = 0; kk < 64; kk++) {
            float pr[4], v0[4], v1[4];
            *(float4*)pr = *(const float4*)&Ps[kk * PADQ + ty * 4];
            *(float4*)v0 = *(const float4*)&Vs[kk * 128 + tx * 8];
            *(float4*)v1 = *(const float4*)&Vs[kk * 128 + tx * 8 + 4];
#pragma unroll
            for (int i = 0; i < 4; i++) {
#pragma unroll
                for (int c = 0; c < 4; c++) {
                    o[i][c]     = fmaf(pr[i], v0[c], o[i][c]);
                    o[i][c + 4] = fmaf(pr[i], v1[c], o[i][c + 4]);
                }
            }
        }
    }

    /* normalize + write out: g_attn[bs][h*128 + d] */
    float* Og = g_attn + ((size_t)(b * S_ + qlo)) * (NH_ * D_) + h * D_;
#pragma unroll
    for (int i = 0; i < 4; i++) {
        int row = ty * 4 + i;
        float inv = 1.f / l_arr[row];
        float4 o0, o1;
        o0.x = o[i][0] * inv; o0.y = o[i][1] * inv;
        o0.z = o[i][2] * inv; o0.w = o[i][3] * inv;
        o1.x = o[i][4] * inv; o1.y = o[i][5] * inv;
        o1.z = o[i][6] * inv; o1.w = o[i][7] * inv;
        float* op = Og + (size_t)row * (NH_ * D_) + tx * 8;
        *(float4*)op       = o0;
        *(float4*)(op + 4) = o1;
    }
}

/* --------------------------------- launch --------------------------------- */
extern "C" void kernel_launch(void* const* d_in, const int* in_sizes, int n_in,
                              void* d_out, int out_size)
{
    const float* hidden = (const float*)d_in[0];
    const float* cosp   = (const float*)d_in[1];
    const float* sinp   = (const float*)d_in[2];
    const float* w_qkv  = (const float*)d_in[3];
    const float* b_qkv  = (const float*)d_in[4];
    const float* w_o    = (const float*)d_in[5];
    const float* b_o    = (const float*)d_in[6];
    float* out = (float*)d_out;

    float *p_qkv = nullptr, *p_attn = nullptr;
    cudaGetSymbolAddress((void**)&p_qkv, g_qkv);
    cudaGetSymbolAddress((void**)&p_attn, g_attn);

    const int ATTN_SMEM = (128 * PADQ * 2 + 64 * PADQ + 64 * 128 + 3 * 64) * 4;
    cudaFuncSetAttribute(attn_kernel,
                         cudaFuncAttributeMaxDynamicSharedMemorySize, ATTN_SMEM);

    /* 1) qkv = hidden @ w_qkv^T + b_qkv */
    sgemm_bias<<<dim3(QKV_OUT_ / 128, BS_ / 128), 256>>>(
        hidden, w_qkv, b_qkv, p_qkv, BS_, QKV_OUT_, HID_);

    /* 2) RoPE + split into [b,h,s,d] layouts */
    rope_split_kernel<<<(BS_ * QKV_OUT_ + 255) / 256, 256>>>(cosp, sinp);

    /* 3) sliding-window flash attention */
    attn_kernel<<<dim3(S_ / 64, NH_, B_), 256, ATTN_SMEM>>>();

    /* 4) out = attn @ w_o^T + b_o */
    sgemm_bias<<<dim3(HID_ / 128, BS_ / 128), 256>>>(
        p_attn, w_o, b_o, out, BS_, HID_, HID_);
}

// round 3
// speedup vs baseline: 1.9731x; 1.9731x over previous
#include <cuda_runtime.h>
#include <cuda_bf16.h>
#include <cstdint>
#include <math.h>

#define B_ 2
#define S_ 1024
#define HID_ 4096
#define NH_ 32
#define NKV_ 8
#define D_ 128
#define WINDOW_ 512
#define QKV_OUT_ ((NH_ + 2 * NKV_) * D_)   /* 6144 */
#define BS_ (B_ * S_)                      /* 2048 */
#define PADQ 68

/* ------------------------- scratch (static device globals) ---------------- */
__device__ float g_qkv[BS_ * QKV_OUT_];
__device__ float g_q[B_ * NH_ * S_ * D_];
__device__ float g_k[B_ * NKV_ * S_ * D_];
__device__ float g_v[B_ * NKV_ * S_ * D_];
__device__ float g_attn[BS_ * (NH_ * D_)];

__device__ __nv_bfloat16 g_h_hi[BS_ * HID_];
__device__ __nv_bfloat16 g_h_lo[BS_ * HID_];
__device__ __nv_bfloat16 g_wq_hi[QKV_OUT_ * HID_];
__device__ __nv_bfloat16 g_wq_lo[QKV_OUT_ * HID_];
__device__ __nv_bfloat16 g_wo_hi[HID_ * HID_];
__device__ __nv_bfloat16 g_wo_lo[HID_ * HID_];
__device__ __nv_bfloat16 g_at_hi[BS_ * HID_];
__device__ __nv_bfloat16 g_at_lo[BS_ * HID_];

/* ============================ PTX helpers (base ISA only) ================= */
__device__ __forceinline__ uint32_t smem_u32(const void* p) {
    return (uint32_t)__cvta_generic_to_shared(p);
}
__device__ __forceinline__ void cp_async16(uint32_t dst, const void* src) {
    asm volatile("cp.async.cg.shared.global [%0], [%1], 16;\n"
                 :: "r"(dst), "l"(src));
}
#define CP_COMMIT() asm volatile("cp.async.commit_group;\n" ::: "memory")
#define CP_WAIT(n)  asm volatile("cp.async.wait_group %0;\n" :: "n"(n) : "memory")

__device__ __forceinline__ void ldsm4(uint32_t* r, uint32_t addr) {
    asm volatile("ldmatrix.sync.aligned.m8n8.x4.shared.b16 {%0,%1,%2,%3}, [%4];"
                 : "=r"(r[0]), "=r"(r[1]), "=r"(r[2]), "=r"(r[3]) : "r"(addr));
}
__device__ __forceinline__ void mma16816(float* d, const uint32_t* a,
                                         const uint32_t* b) {
    asm volatile("mma.sync.aligned.m16n8k16.row.col.f32.bf16.bf16.f32 "
                 "{%0,%1,%2,%3}, {%4,%5,%6,%7}, {%8,%9}, {%0,%1,%2,%3};"
                 : "+f"(d[0]), "+f"(d[1]), "+f"(d[2]), "+f"(d[3])
                 : "r"(a[0]), "r"(a[1]), "r"(a[2]), "r"(a[3]),
                   "r"(b[0]), "r"(b[1]));
}

/* ==================== fp32 -> bf16 hi/lo split ============================ */
__global__ void cvt_split(const float* __restrict__ x,
                          __nv_bfloat16* __restrict__ hi,
                          __nv_bfloat16* __restrict__ lo, int n4)
{
    int i = blockIdx.x * blockDim.x + threadIdx.x;
    if (i >= n4) return;
    float4 v = ((const float4*)x)[i];
    __nv_bfloat16 h0 = __float2bfloat16(v.x);
    __nv_bfloat16 h1 = __float2bfloat16(v.y);
    __nv_bfloat16 h2 = __float2bfloat16(v.z);
    __nv_bfloat16 h3 = __float2bfloat16(v.w);
    __nv_bfloat16 l0 = __float2bfloat16(v.x - __bfloat162float(h0));
    __nv_bfloat16 l1 = __float2bfloat16(v.y - __bfloat162float(h1));
    __nv_bfloat16 l2 = __float2bfloat16(v.z - __bfloat162float(h2));
    __nv_bfloat16 l3 = __float2bfloat16(v.w - __bfloat162float(h3));
    __nv_bfloat162 hv0 = {h0, h1}, hv1 = {h2, h3};
    __nv_bfloat162 lv0 = {l0, l1}, lv1 = {l2, l3};
    uint2 hw, lw;
    hw.x = *(uint32_t*)&hv0; hw.y = *(uint32_t*)&hv1;
    lw.x = *(uint32_t*)&lv0; lw.y = *(uint32_t*)&lv1;
    ((uint2*)hi)[i] = hw;
    ((uint2*)lo)[i] = lw;
}

/* ============== HMMA GEMM: C = A*B^T + bias, 3xBF16 split ================= */
/* A: [M,K] hi/lo bf16. B: [N,K] hi/lo bf16. C: fp32 [M,N].
   CTA 128x128, 512 thr (16 warps, 4x4 grid of 32x32 warp tiles), BK=32,
   double-buffered cp.async. Smem rows padded to 40 bf16 (80B). */
#define GTILE (128 * 40)                 /* bf16 elems per matrix per stage */
#define GSTAGE_B (4 * GTILE * 2)         /* bytes per stage (Ah,Al,Bh,Bl)   */
#define GSMEM (2 * GSTAGE_B)             /* 81920 B                          */

__global__ void __launch_bounds__(512) gemm_mma_bf16x3(
    const __nv_bfloat16* __restrict__ Ah, const __nv_bfloat16* __restrict__ Al,
    const __nv_bfloat16* __restrict__ Bh, const __nv_bfloat16* __restrict__ Bl,
    const float* __restrict__ bias, float* __restrict__ C, int N, int K)
{
    extern __shared__ __nv_bfloat16 smem[];
    const uint32_t sb = smem_u32(smem);

    const int tid  = threadIdx.x;
    const int lane = tid & 31;
    const int wid  = tid >> 5;
    const int wy   = wid >> 2;          /* m warp 0..3 */
    const int wx   = wid & 3;           /* n warp 0..3 */
    const int m0   = blockIdx.y * 128;
    const int n0   = blockIdx.x * 128;
    const int KT   = K / 32;

    /* loader indices: each thread one 16B chunk per matrix */
    const int lr = tid >> 2;            /* row 0..127 */
    const int lc = (tid & 3) * 8;       /* col 0,8,16,24 */
    const uint32_t doff = (uint32_t)(lr * 40 + lc) * 2;

    float acc[2][4][4];
#pragma unroll
    for (int mt = 0; mt < 2; mt++)
#pragma unroll
        for (int nt = 0; nt < 4; nt++)
#pragma unroll
            for (int j = 0; j < 4; j++) acc[mt][nt][j] = 0.f;

    /* ldmatrix source addresses (within a stage, per matrix) */
    const int a_row = wy * 32 + (lane & 15);
    const int a_col = (lane >> 4) * 8;
    const uint32_t a_off = (uint32_t)(a_row * 40 + a_col) * 2;
    const int b_row = wx * 32 + ((lane >> 4) << 3) + (lane & 7);
    const int b_col = ((lane >> 3) & 1) * 8;
    const uint32_t b_off = (uint32_t)(b_row * 40 + b_col) * 2;

#define LOAD_STAGE(kt, st) do {                                         \
        const int k0_ = (kt) * 32;                                      \
        const uint32_t s0_ = sb + (st) * GSTAGE_B + doff;               \
        const size_t asrc_ = (size_t)(m0 + lr) * K + k0_ + lc;          \
        const size_t bsrc_ = (size_t)(n0 + lr) * K + k0_ + lc;          \
        cp_async16(s0_ + 0 * GTILE * 2, Ah + asrc_);                    \
        cp_async16(s0_ + 1 * GTILE * 2, Al + asrc_);                    \
        cp_async16(s0_ + 2 * GTILE * 2, Bh + bsrc_);                    \
        cp_async16(s0_ + 3 * GTILE * 2, Bl + bsrc_);                    \
    } while (0)

    LOAD_STAGE(0, 0);
    CP_COMMIT();

    for (int kt = 0; kt < KT; kt++) {
        if (kt + 1 < KT) {
            LOAD_STAGE(kt + 1, (kt + 1) & 1);
            CP_COMMIT();
            CP_WAIT(1);
        } else {
            CP_WAIT(0);
        }
        __syncthreads();

        const uint32_t stb = sb + (kt & 1) * GSTAGE_B;
#pragma unroll
        for (int ks = 0; ks < 32; ks += 16) {
            const uint32_t kso = (uint32_t)ks * 2;
            uint32_t ah[2][4], al[2][4], bh[4][2], bl[4][2];
#pragma unroll
            for (int mt = 0; mt < 2; mt++) {
                uint32_t ao = stb + a_off + (uint32_t)(mt * 16 * 40) * 2 + kso;
                ldsm4(ah[mt], ao);
                ldsm4(al[mt], ao + GTILE * 2);
            }
#pragma unroll
            for (int nt2 = 0; nt2 < 2; nt2++) {
                uint32_t bo = stb + 2 * GTILE * 2 + b_off +
                              (uint32_t)(nt2 * 16 * 40) * 2 + kso;
                uint32_t r[4];
                ldsm4(r, bo);
                bh[nt2 * 2][0] = r[0]; bh[nt2 * 2][1] = r[1];
                bh[nt2 * 2 + 1][0] = r[2]; bh[nt2 * 2 + 1][1] = r[3];
                ldsm4(r, bo + GTILE * 2);
                bl[nt2 * 2][0] = r[0]; bl[nt2 * 2][1] = r[1];
                bl[nt2 * 2 + 1][0] = r[2]; bl[nt2 * 2 + 1][1] = r[3];
            }
#pragma unroll
            for (int mt = 0; mt < 2; mt++)
#pragma unroll
                for (int nt = 0; nt < 4; nt++)
                    mma16816(acc[mt][nt], ah[mt], bh[nt]);
#pragma unroll
            for (int mt = 0; mt < 2; mt++)
#pragma unroll
                for (int nt = 0; nt < 4; nt++)
                    mma16816(acc[mt][nt], ah[mt], bl[nt]);
#pragma unroll
            for (int mt = 0; mt < 2; mt++)
#pragma unroll
                for (int nt = 0; nt < 4; nt++)
                    mma16816(acc[mt][nt], al[mt], bh[nt]);
        }
        __syncthreads();
    }
#undef LOAD_STAGE

    /* epilogue: write 32x32 warp tile */
#pragma unroll
    for (int mt = 0; mt < 2; mt++) {
        int row0 = m0 + wy * 32 + mt * 16 + (lane >> 2);
#pragma unroll
        for (int nt = 0; nt < 4; nt++) {
            int col = n0 + wx * 32 + nt * 8 + (lane & 3) * 2;
            float b0 = bias[col], b1 = bias[col + 1];
            float2 v0 = {acc[mt][nt][0] + b0, acc[mt][nt][1] + b1};
            float2 v1 = {acc[mt][nt][2] + b0, acc[mt][nt][3] + b1};
            *(float2*)(C + (size_t)row0 * N + col)       = v0;
            *(float2*)(C + (size_t)(row0 + 8) * N + col) = v1;
        }
    }
}

/* ---------------- RoPE + split qkv into attention-friendly layouts -------- */
__global__ void rope_split_kernel(const float* __restrict__ cosp,
                                  const float* __restrict__ sinp)
{
    int idx = blockIdx.x * blockDim.x + threadIdx.x;
    if (idx >= BS_ * QKV_OUT_) return;
    int col = idx % QKV_OUT_;
    int bs  = idx / QKV_OUT_;
    int b   = bs / S_;
    int s   = bs - b * S_;
    int d   = col & (D_ - 1);
    float v = g_qkv[idx];

    if (col < NH_ * D_) {
        int h = col >> 7;
        float c  = cosp[s * D_ + d];
        float sn = sinp[s * D_ + d];
        float partner = g_qkv[(size_t)bs * QKV_OUT_ + (col ^ 64)];
        float r = (d < 64) ? -partner : partner;
        g_q[(((size_t)b * NH_ + h) * S_ + s) * D_ + d] = v * c + r * sn;
    } else if (col < (NH_ + NKV_) * D_) {
        int kvh = (col - NH_ * D_) >> 7;
        float c  = cosp[s * D_ + d];
        float sn = sinp[s * D_ + d];
        float partner = g_qkv[(size_t)bs * QKV_OUT_ + (col ^ 64)];
        float r = (d < 64) ? -partner : partner;
        g_k[(((size_t)b * NKV_ + kvh) * S_ + s) * D_ + d] = v * c + r * sn;
    } else {
        int kvh = (col - (NH_ + NKV_) * D_) >> 7;
        g_v[(((size_t)b * NKV_ + kvh) * S_ + s) * D_ + d] = v;
    }
}

/* -------- flash attention, sliding window 512, GQA (4 q heads / kv) ------- */
__global__ void __launch_bounds__(256) attn_kernel()
{
    const int qb  = blockIdx.x;
    const int h   = blockIdx.y;
    const int b   = blockIdx.z;
    const int kvh = h >> 2;

    extern __shared__ float smf[];
    float* Qs     = smf;
    float* Ks     = Qs + 128 * PADQ;
    float* Ps     = Ks + 128 * PADQ;
    float* Vs     = Ps + 64 * PADQ;
    float* m_arr  = Vs + 64 * 128;
    float* l_arr  = m_arr + 64;
    float* sc_arr = l_arr + 64;

    const int tid = threadIdx.x;
    const int ty  = tid >> 4, tx = tid & 15;
    const int qlo = qb * 64;
    const float SCALE = 0.08838834764831845f;

    const float* Qg = g_q + (((size_t)b * NH_ + h) * S_ + qlo) * D_;
    for (int e = tid * 4; e < 64 * 128; e += 1024) {
        int q = e >> 7, d = e & 127;
        float4 v = *(const float4*)(Qg + e);
        Qs[(d + 0) * PADQ + q] = v.x * SCALE;
        Qs[(d + 1) * PADQ + q] = v.y * SCALE;
        Qs[(d + 2) * PADQ + q] = v.z * SCALE;
        Qs[(d + 3) * PADQ + q] = v.w * SCALE;
    }
    if (tid < 64) { m_arr[tid] = -1e30f; l_arr[tid] = 0.f; }

    float o[4][8];
#pragma unroll
    for (int i = 0; i < 4; i++)
#pragma unroll
        for (int c = 0; c < 8; c++) o[i][c] = 0.f;

    int ks = qlo - (WINDOW_ - 1);
    if (ks < 0) ks = 0;
    const int kb0 = ks >> 6, kb1 = qb;

    const float* Kg = g_k + (((size_t)b * NKV_ + kvh) * S_) * D_;
    const float* Vg = g_v + (((size_t)b * NKV_ + kvh) * S_) * D_;

    for (int kb = kb0; kb <= kb1; kb++) {
        __syncthreads();
        const int kbase = kb * 64;
        for (int e = tid * 4; e < 64 * 128; e += 1024) {
            int r = e >> 7, d = e & 127;
            float4 kv4 = *(const float4*)(Kg + (size_t)kbase * D_ + e);
            Ks[(d + 0) * PADQ + r] = kv4.x;
            Ks[(d + 1) * PADQ + r] = kv4.y;
            Ks[(d + 2) * PADQ + r] = kv4.z;
            Ks[(d + 3) * PADQ + r] = kv4.w;
            float4 vv4 = *(const float4*)(Vg + (size_t)kbase * D_ + e);
            *(float4*)&Vs[r * 128 + d] = vv4;
        }
        __syncthreads();

        float sacc[4][4];
#pragma unroll
        for (int i = 0; i < 4; i++)
#pragma unroll
            for (int j = 0; j < 4; j++) sacc[i][j] = 0.f;

#pragma unroll 8
        for (int kk = 0; kk < 128; kk++) {
            float qr[4], kr[4];
            *(float4*)qr = *(const float4*)&Qs[kk * PADQ + ty * 4];
            *(float4*)kr = *(const float4*)&Ks[kk * PADQ + tx * 4];
#pragma unroll
            for (int i = 0; i < 4; i++)
#pragma unroll
                for (int j = 0; j < 4; j++)
                    sacc[i][j] = fmaf(qr[i], kr[j], sacc[i][j]);
        }

#pragma unroll
        for (int j = 0; j < 4; j++) {
            int kg = kbase + tx * 4 + j;
#pragma unroll
            for (int i = 0; i < 4; i++) {
                int qg = qlo + ty * 4 + i;
                bool ok = (kg <= qg) && (qg - kg < WINDOW_);
                Ps[(tx * 4 + j) * PADQ + ty * 4 + i] = ok ? sacc[i][j] : -1e30f;
            }
        }
        __syncthreads();

        if (tid < 64) {
            const int q = tid;
            float mo = m_arr[q];
            float mx = mo;
#pragma unroll 8
            for (int k = 0; k < 64; k++) mx = fmaxf(mx, Ps[k * PADQ + q]);
            float l_add = 0.f;
#pragma unroll 4
            for (int k = 0; k < 64; k++) {
                float sv = Ps[k * PADQ + q];
                float p  = (sv > -1e29f) ? __expf(sv - mx) : 0.f;
                Ps[k * PADQ + q] = p;
                l_add += p;
            }
            float sf = __expf(mo - mx);
            l_arr[q]  = l_arr[q] * sf + l_add;
            m_arr[q]  = mx;
            sc_arr[q] = sf;
        }
        __syncthreads();

        float sf[4];
#pragma unroll
        for (int i = 0; i < 4; i++) sf[i] = sc_arr[ty * 4 + i];
#pragma unroll
        for (int i = 0; i < 4; i++)
#pragma unroll
            for (int c = 0; c < 8; c++) o[i][c] *= sf[i];

#pragma unroll 8
        for (int kk = 0; kk < 64; kk++) {
            float pr[4], v0[4], v1[4];
            *(float4*)pr = *(const float4*)&Ps[kk * PADQ + ty * 4];
            *(float4*)v0 = *(const float4*)&Vs[kk * 128 + tx * 8];
            *(float4*)v1 = *(const float4*)&Vs[kk * 128 + tx * 8 + 4];
#pragma unroll
            for (int i = 0; i < 4; i++) {
#pragma unroll
                for (int c = 0; c < 4; c++) {
                    o[i][c]     = fmaf(pr[i], v0[c], o[i][c]);
                    o[i][c + 4] = fmaf(pr[i], v1[c], o[i][c + 4]);
                }
            }
        }
    }

    float* Og = g_attn + ((size_t)(b * S_ + qlo)) * (NH_ * D_) + h * D_;
#pragma unroll
    for (int i = 0; i < 4; i++) {
        int row = ty * 4 + i;
        float inv = 1.f / l_arr[row];
        float4 o0, o1;
        o0.x = o[i][0] * inv; o0.y = o[i][1] * inv;
        o0.z = o[i][2] * inv; o0.w = o[i][3] * inv;
        o1.x = o[i][4] * inv; o1.y = o[i][5] * inv;
        o1.z = o[i][6] * inv; o1.w = o[i][7] * inv;
        float* op = Og + (size_t)row * (NH_ * D_) + tx * 8;
        *(float4*)op       = o0;
        *(float4*)(op + 4) = o1;
    }
}

/* --------------------------------- launch --------------------------------- */
extern "C" void kernel_launch(void* const* d_in, const int* in_sizes, int n_in,
                              void* d_out, int out_size)
{
    const float* hidden = (const float*)d_in[0];
    const float* cosp   = (const float*)d_in[1];
    const float* sinp   = (const float*)d_in[2];
    const float* w_qkv  = (const float*)d_in[3];
    const float* b_qkv  = (const float*)d_in[4];
    const float* w_o    = (const float*)d_in[5];
    const float* b_o    = (const float*)d_in[6];
    float* out = (float*)d_out;

    float *p_qkv, *p_attn;
    __nv_bfloat16 *p_h_hi, *p_h_lo, *p_wq_hi, *p_wq_lo, *p_wo_hi, *p_wo_lo,
                  *p_at_hi, *p_at_lo;
    cudaGetSymbolAddress((void**)&p_qkv, g_qkv);
    cudaGetSymbolAddress((void**)&p_attn, g_attn);
    cudaGetSymbolAddress((void**)&p_h_hi, g_h_hi);
    cudaGetSymbolAddress((void**)&p_h_lo, g_h_lo);
    cudaGetSymbolAddress((void**)&p_wq_hi, g_wq_hi);
    cudaGetSymbolAddress((void**)&p_wq_lo, g_wq_lo);
    cudaGetSymbolAddress((void**)&p_wo_hi, g_wo_hi);
    cudaGetSymbolAddress((void**)&p_wo_lo, g_wo_lo);
    cudaGetSymbolAddress((void**)&p_at_hi, g_at_hi);
    cudaGetSymbolAddress((void**)&p_at_lo, g_at_lo);

    const int ATTN_SMEM = (128 * PADQ * 2 + 64 * PADQ + 64 * 128 + 3 * 64) * 4;
    cudaFuncSetAttribute(attn_kernel,
                         cudaFuncAttributeMaxDynamicSharedMemorySize, ATTN_SMEM);
    cudaFuncSetAttribute(gemm_mma_bf16x3,
                         cudaFuncAttributeMaxDynamicSharedMemorySize, GSMEM);

    /* converts */
    cvt_split<<<(BS_ * HID_ / 4 + 255) / 256, 256>>>(hidden, p_h_hi, p_h_lo,
                                                     BS_ * HID_ / 4);
    cvt_split<<<(QKV_OUT_ * HID_ / 4 + 255) / 256, 256>>>(w_qkv, p_wq_hi, p_wq_lo,
                                                          QKV_OUT_ * HID_ / 4);
    cvt_split<<<(HID_ * HID_ / 4 + 255) / 256, 256>>>(w_o, p_wo_hi, p_wo_lo,
                                                      HID_ * HID_ / 4);

    /* 1) qkv = hidden @ w_qkv^T + b_qkv  (HMMA, 3xBF16) */
    gemm_mma_bf16x3<<<dim3(QKV_OUT_ / 128, BS_ / 128), 512, GSMEM>>>(
        p_h_hi, p_h_lo, p_wq_hi, p_wq_lo, b_qkv, p_qkv, QKV_OUT_, HID_);

    /* 2) RoPE + split */
    rope_split_kernel<<<(BS_ * QKV_OUT_ + 255) / 256, 256>>>(cosp, sinp);

    /* 3) attention */
    attn_kernel<<<dim3(S_ / 64, NH_, B_), 256, ATTN_SMEM>>>();

    /* 4) convert attn, then out = attn @ w_o^T + b_o */
    cvt_split<<<(BS_ * HID_ / 4 + 255) / 256, 256>>>(p_attn, p_at_hi, p_at_lo,
                                                     BS_ * HID_ / 4);
    gemm_mma_bf16x3<<<dim3(HID_ / 128, BS_ / 128), 512, GSMEM>>>(
        p_at_hi, p_at_lo, p_wo_hi, p_wo_lo, b_o, out, HID_, HID_);
}

// round 4
// speedup vs baseline: 2.5486x; 1.2916x over previous
#include <cuda_runtime.h>
#include <cuda_bf16.h>
#include <cstdint>
#include <math.h>

#define B_ 2
#define S_ 1024
#define HID_ 4096
#define NH_ 32
#define NKV_ 8
#define D_ 128
#define WINDOW_ 512
#define QKV_OUT_ ((NH_ + 2 * NKV_) * D_)   /* 6144 */
#define BS_ (B_ * S_)                      /* 2048 */

/* ------------------------- scratch (static device globals) ---------------- */
__device__ float g_qkv[BS_ * QKV_OUT_];
__device__ float g_attn[BS_ * (NH_ * D_)];

__device__ __nv_bfloat16 g_qh[B_ * NH_ * S_ * D_];
__device__ __nv_bfloat16 g_ql[B_ * NH_ * S_ * D_];
__device__ __nv_bfloat16 g_kh[B_ * NKV_ * S_ * D_];
__device__ __nv_bfloat16 g_kl[B_ * NKV_ * S_ * D_];
__device__ __nv_bfloat16 g_vh[B_ * NKV_ * S_ * D_];
__device__ __nv_bfloat16 g_vl[B_ * NKV_ * S_ * D_];

__device__ __nv_bfloat16 g_h_hi[BS_ * HID_];
__device__ __nv_bfloat16 g_h_lo[BS_ * HID_];
__device__ __nv_bfloat16 g_wq_hi[QKV_OUT_ * HID_];
__device__ __nv_bfloat16 g_wq_lo[QKV_OUT_ * HID_];
__device__ __nv_bfloat16 g_wo_hi[HID_ * HID_];
__device__ __nv_bfloat16 g_wo_lo[HID_ * HID_];
__device__ __nv_bfloat16 g_at_hi[BS_ * HID_];
__device__ __nv_bfloat16 g_at_lo[BS_ * HID_];

/* ============================ PTX helpers (base ISA only) ================= */
__device__ __forceinline__ uint32_t smem_u32(const void* p) {
    return (uint32_t)__cvta_generic_to_shared(p);
}
__device__ __forceinline__ void cp_async16(uint32_t dst, const void* src) {
    asm volatile("cp.async.cg.shared.global [%0], [%1], 16;\n"
                 :: "r"(dst), "l"(src));
}
#define CP_COMMIT() asm volatile("cp.async.commit_group;\n" ::: "memory")
#define CP_WAIT(n)  asm volatile("cp.async.wait_group %0;\n" :: "n"(n) : "memory")

__device__ __forceinline__ void ldsm4(uint32_t* r, uint32_t addr) {
    asm volatile("ldmatrix.sync.aligned.m8n8.x4.shared.b16 {%0,%1,%2,%3}, [%4];"
                 : "=r"(r[0]), "=r"(r[1]), "=r"(r[2]), "=r"(r[3]) : "r"(addr));
}
__device__ __forceinline__ void ldsm4t(uint32_t* r, uint32_t addr) {
    asm volatile("ldmatrix.sync.aligned.m8n8.x4.trans.shared.b16 {%0,%1,%2,%3}, [%4];"
                 : "=r"(r[0]), "=r"(r[1]), "=r"(r[2]), "=r"(r[3]) : "r"(addr));
}
__device__ __forceinline__ void mma16816(float* d, const uint32_t* a,
                                         const uint32_t* b) {
    asm volatile("mma.sync.aligned.m16n8k16.row.col.f32.bf16.bf16.f32 "
                 "{%0,%1,%2,%3}, {%4,%5,%6,%7}, {%8,%9}, {%0,%1,%2,%3};"
                 : "+f"(d[0]), "+f"(d[1]), "+f"(d[2]), "+f"(d[3])
                 : "r"(a[0]), "r"(a[1]), "r"(a[2]), "r"(a[3]),
                   "r"(b[0]), "r"(b[1]));
}
__device__ __forceinline__ float ex2f(float x) {
    float y;
    asm("ex2.approx.f32 %0, %1;" : "=f"(y) : "f"(x));
    return y;
}
__device__ __forceinline__ void pack_hilo(float x, float y,
                                          uint32_t& hw, uint32_t& lw) {
    __nv_bfloat162 h = __float22bfloat162_rn(make_float2(x, y));
    float2 hf = __bfloat1622float2(h);
    __nv_bfloat162 l = __float22bfloat162_rn(make_float2(x - hf.x, y - hf.y));
    hw = *(uint32_t*)&h;
    lw = *(uint32_t*)&l;
}

/* ==================== fp32 -> bf16 hi/lo split ============================ */
__global__ void cvt_split(const float* __restrict__ x,
                          __nv_bfloat16* __restrict__ hi,
                          __nv_bfloat16* __restrict__ lo, int n4)
{
    int i = blockIdx.x * blockDim.x + threadIdx.x;
    if (i >= n4) return;
    float4 v = ((const float4*)x)[i];
    __nv_bfloat16 h0 = __float2bfloat16(v.x);
    __nv_bfloat16 h1 = __float2bfloat16(v.y);
    __nv_bfloat16 h2 = __float2bfloat16(v.z);
    __nv_bfloat16 h3 = __float2bfloat16(v.w);
    __nv_bfloat16 l0 = __float2bfloat16(v.x - __bfloat162float(h0));
    __nv_bfloat16 l1 = __float2bfloat16(v.y - __bfloat162float(h1));
    __nv_bfloat16 l2 = __float2bfloat16(v.z - __bfloat162float(h2));
    __nv_bfloat16 l3 = __float2bfloat16(v.w - __bfloat162float(h3));
    __nv_bfloat162 hv0 = {h0, h1}, hv1 = {h2, h3};
    __nv_bfloat162 lv0 = {l0, l1}, lv1 = {l2, l3};
    uint2 hw, lw;
    hw.x = *(uint32_t*)&hv0; hw.y = *(uint32_t*)&hv1;
    lw.x = *(uint32_t*)&lv0; lw.y = *(uint32_t*)&lv1;
    ((uint2*)hi)[i] = hw;
    ((uint2*)lo)[i] = lw;
}

/* ============== HMMA GEMM: C = A*B^T + bias, 3xBF16 split ================= */
#define GTILE (128 * 40)
#define GSTAGE_B (4 * GTILE * 2)
#define GSMEM (2 * GSTAGE_B)

__global__ void __launch_bounds__(512) gemm_mma_bf16x3(
    const __nv_bfloat16* __restrict__ Ah, const __nv_bfloat16* __restrict__ Al,
    const __nv_bfloat16* __restrict__ Bh, const __nv_bfloat16* __restrict__ Bl,
    const float* __restrict__ bias, float* __restrict__ C, int N, int K)
{
    extern __shared__ __nv_bfloat16 smem[];
    const uint32_t sb = smem_u32(smem);

    const int tid  = threadIdx.x;
    const int lane = tid & 31;
    const int wid  = tid >> 5;
    const int wy   = wid >> 2;
    const int wx   = wid & 3;
    const int m0   = blockIdx.y * 128;
    const int n0   = blockIdx.x * 128;
    const int KT   = K / 32;

    const int lr = tid >> 2;
    const int lc = (tid & 3) * 8;
    const uint32_t doff = (uint32_t)(lr * 40 + lc) * 2;

    float acc[2][4][4];
#pragma unroll
    for (int mt = 0; mt < 2; mt++)
#pragma unroll
        for (int nt = 0; nt < 4; nt++)
#pragma unroll
            for (int j = 0; j < 4; j++) acc[mt][nt][j] = 0.f;

    const int a_row = wy * 32 + (lane & 15);
    const int a_col = (lane >> 4) * 8;
    const uint32_t a_off = (uint32_t)(a_row * 40 + a_col) * 2;
    const int b_row = wx * 32 + ((lane >> 4) << 3) + (lane & 7);
    const int b_col = ((lane >> 3) & 1) * 8;
    const uint32_t b_off = (uint32_t)(b_row * 40 + b_col) * 2;

#define LOAD_STAGE(kt, st) do {                                         \
        const int k0_ = (kt) * 32;                                      \
        const uint32_t s0_ = sb + (st) * GSTAGE_B + doff;               \
        const size_t asrc_ = (size_t)(m0 + lr) * K + k0_ + lc;          \
        const size_t bsrc_ = (size_t)(n0 + lr) * K + k0_ + lc;          \
        cp_async16(s0_ + 0 * GTILE * 2, Ah + asrc_);                    \
        cp_async16(s0_ + 1 * GTILE * 2, Al + asrc_);                    \
        cp_async16(s0_ + 2 * GTILE * 2, Bh + bsrc_);                    \
        cp_async16(s0_ + 3 * GTILE * 2, Bl + bsrc_);                    \
    } while (0)

    LOAD_STAGE(0, 0);
    CP_COMMIT();

    for (int kt = 0; kt < KT; kt++) {
        if (kt + 1 < KT) {
            LOAD_STAGE(kt + 1, (kt + 1) & 1);
            CP_COMMIT();
            CP_WAIT(1);
        } else {
            CP_WAIT(0);
        }
        __syncthreads();

        const uint32_t stb = sb + (kt & 1) * GSTAGE_B;
#pragma unroll
        for (int ks = 0; ks < 32; ks += 16) {
            const uint32_t kso = (uint32_t)ks * 2;
            uint32_t ah[2][4], al[2][4], bh[4][2], bl[4][2];
#pragma unroll
            for (int mt = 0; mt < 2; mt++) {
                uint32_t ao = stb + a_off + (uint32_t)(mt * 16 * 40) * 2 + kso;
                ldsm4(ah[mt], ao);
                ldsm4(al[mt], ao + GTILE * 2);
            }
#pragma unroll
            for (int nt2 = 0; nt2 < 2; nt2++) {
                uint32_t bo = stb + 2 * GTILE * 2 + b_off +
                              (uint32_t)(nt2 * 16 * 40) * 2 + kso;
                uint32_t r[4];
                ldsm4(r, bo);
                bh[nt2 * 2][0] = r[0]; bh[nt2 * 2][1] = r[1];
                bh[nt2 * 2 + 1][0] = r[2]; bh[nt2 * 2 + 1][1] = r[3];
                ldsm4(r, bo + GTILE * 2);
                bl[nt2 * 2][0] = r[0]; bl[nt2 * 2][1] = r[1];
                bl[nt2 * 2 + 1][0] = r[2]; bl[nt2 * 2 + 1][1] = r[3];
            }
#pragma unroll
            for (int mt = 0; mt < 2; mt++)
#pragma unroll
                for (int nt = 0; nt < 4; nt++)
                    mma16816(acc[mt][nt], ah[mt], bh[nt]);
#pragma unroll
            for (int mt = 0; mt < 2; mt++)
#pragma unroll
                for (int nt = 0; nt < 4; nt++)
                    mma16816(acc[mt][nt], ah[mt], bl[nt]);
#pragma unroll
            for (int mt = 0; mt < 2; mt++)
#pragma unroll
                for (int nt = 0; nt < 4; nt++)
                    mma16816(acc[mt][nt], al[mt], bh[nt]);
        }
        __syncthreads();
    }
#undef LOAD_STAGE

#pragma unroll
    for (int mt = 0; mt < 2; mt++) {
        int row0 = m0 + wy * 32 + mt * 16 + (lane >> 2);
#pragma unroll
        for (int nt = 0; nt < 4; nt++) {
            int col = n0 + wx * 32 + nt * 8 + (lane & 3) * 2;
            float b0 = bias[col], b1 = bias[col + 1];
            float2 v0 = {acc[mt][nt][0] + b0, acc[mt][nt][1] + b1};
            float2 v1 = {acc[mt][nt][2] + b0, acc[mt][nt][3] + b1};
            *(float2*)(C + (size_t)row0 * N + col)       = v0;
            *(float2*)(C + (size_t)(row0 + 8) * N + col) = v1;
        }
    }
}

/* -------- RoPE + split qkv into bf16 hi/lo attention layouts -------------- */
__global__ void rope_split_kernel(const float* __restrict__ cosp,
                                  const float* __restrict__ sinp)
{
    int idx = blockIdx.x * blockDim.x + threadIdx.x;
    if (idx >= BS_ * QKV_OUT_) return;
    int col = idx % QKV_OUT_;
    int bs  = idx / QKV_OUT_;
    int b   = bs / S_;
    int s   = bs - b * S_;
    int d   = col & (D_ - 1);
    float v = g_qkv[idx];
    const float SCALE = 0.08838834764831845f;  /* 1/sqrt(128) */

    float val;
    size_t dst;
    __nv_bfloat16 *ph, *pl;
    if (col < NH_ * D_) {
        int h = col >> 7;
        float c  = cosp[s * D_ + d];
        float sn = sinp[s * D_ + d];
        float partner = g_qkv[(size_t)bs * QKV_OUT_ + (col ^ 64)];
        float r = (d < 64) ? -partner : partner;
        val = (v * c + r * sn) * SCALE;
        dst = (((size_t)b * NH_ + h) * S_ + s) * D_ + d;
        ph = g_qh; pl = g_ql;
    } else if (col < (NH_ + NKV_) * D_) {
        int kvh = (col - NH_ * D_) >> 7;
        float c  = cosp[s * D_ + d];
        float sn = sinp[s * D_ + d];
        float partner = g_qkv[(size_t)bs * QKV_OUT_ + (col ^ 64)];
        float r = (d < 64) ? -partner : partner;
        val = v * c + r * sn;
        dst = (((size_t)b * NKV_ + kvh) * S_ + s) * D_ + d;
        ph = g_kh; pl = g_kl;
    } else {
        int kvh = (col - (NH_ + NKV_) * D_) >> 7;
        val = v;
        dst = (((size_t)b * NKV_ + kvh) * S_ + s) * D_ + d;
        ph = g_vh; pl = g_vl;
    }
    __nv_bfloat16 hv = __float2bfloat16(val);
    ph[dst] = hv;
    pl[dst] = __float2bfloat16(val - __bfloat162float(hv));
}

/* ============ HMMA flash attention (sliding window, GQA) ================== */
/* q-tile 128, kv-tile 64, 8 warps (16 q rows each), 3xBF16 split everywhere */
#define AT_PAD 136                        /* padded row length in bf16 elems */
#define AQ_L   (128 * AT_PAD)             /* Q-lo offset (elems) */
#define AST0   (2 * 128 * AT_PAD)         /* stages start (elems) */
#define AMAT   (64 * AT_PAD)              /* one K/V matrix (elems) */
#define ASTAGE (4 * AMAT)                 /* Kh,Kl,Vh,Vl per stage */
#define ATTN_SMEM_B ((AST0 + 2 * ASTAGE) * 2)   /* 208896 bytes */
#define LOG2E 1.4426950408889634f

__global__ void __launch_bounds__(256, 1) attn_mma()
{
    const int qbx = blockIdx.x, h = blockIdx.y, b = blockIdx.z;
    const int kvh = h >> 2;
    const int qlo = qbx * 128;

    extern __shared__ __nv_bfloat16 asmem[];
    const uint32_t sb = smem_u32(asmem);
    const int tid = threadIdx.x, lane = tid & 31, w = tid >> 5;

    const __nv_bfloat16* Qhg = g_qh + (((size_t)b * NH_ + h) * S_ + qlo) * D_;
    const __nv_bfloat16* Qlg = g_ql + (((size_t)b * NH_ + h) * S_ + qlo) * D_;
    const __nv_bfloat16* Khg = g_kh + ((size_t)b * NKV_ + kvh) * S_ * D_;
    const __nv_bfloat16* Klg = g_kl + ((size_t)b * NKV_ + kvh) * S_ * D_;
    const __nv_bfloat16* Vhg = g_vh + ((size_t)b * NKV_ + kvh) * S_ * D_;
    const __nv_bfloat16* Vlg = g_vl + ((size_t)b * NKV_ + kvh) * S_ * D_;

    /* Q tile load (hi/lo) */
    for (int c = tid; c < 2048; c += 256) {
        int row = c >> 4, ch = c & 15;
        uint32_t dq = sb + (uint32_t)(row * AT_PAD + ch * 8) * 2;
        size_t src = (size_t)row * D_ + ch * 8;
        cp_async16(dq, Qhg + src);
        cp_async16(dq + AQ_L * 2, Qlg + src);
    }

#define LOAD_KV(kb, st) do {                                            \
        const int kbase_ = (kb) * 64;                                   \
        const uint32_t s0_ = sb + (uint32_t)(AST0 + (st) * ASTAGE) * 2; \
        for (int c = tid; c < 1024; c += 256) {                         \
            int row_ = c >> 4, ch_ = c & 15;                            \
            uint32_t d_ = s0_ + (uint32_t)(row_ * AT_PAD + ch_ * 8) * 2;\
            size_t src_ = (size_t)(kbase_ + row_) * D_ + ch_ * 8;       \
            cp_async16(d_,                Khg + src_);                  \
            cp_async16(d_ + AMAT * 2,     Klg + src_);                  \
            cp_async16(d_ + 2 * AMAT * 2, Vhg + src_);                  \
            cp_async16(d_ + 3 * AMAT * 2, Vlg + src_);                  \
        } } while (0)

    int kstart = qlo - (WINDOW_ - 1);
    if (kstart < 0) kstart = 0;
    const int kb0 = kstart >> 6;
    const int kb1 = (qlo + 127) >> 6;

    LOAD_KV(kb0, 0);
    CP_COMMIT();

    float oacc[16][4];
#pragma unroll
    for (int nf = 0; nf < 16; nf++)
#pragma unroll
        for (int j = 0; j < 4; j++) oacc[nf][j] = 0.f;
    float m0 = -1e30f, m1 = -1e30f, l0 = 0.f, l1 = 0.f;

    const int qg0 = qlo + w * 16 + (lane >> 2);
    const int qg1 = qg0 + 8;
    const uint32_t qrow_off =
        (uint32_t)((w * 16 + (lane & 15)) * AT_PAD + (lane >> 4) * 8) * 2;
    const uint32_t krow_off =
        (uint32_t)((((lane >> 4) << 3) + (lane & 7)) * AT_PAD +
                   ((lane >> 3) & 1) * 8) * 2;
    const uint32_t vrow_off =
        (uint32_t)((lane & 15) * AT_PAD + (lane >> 4) * 8) * 2;

    for (int kb = kb0; kb <= kb1; kb++) {
        const int st = (kb - kb0) & 1;
        if (kb < kb1) {
            LOAD_KV(kb + 1, st ^ 1);
            CP_COMMIT();
            CP_WAIT(1);
        } else {
            CP_WAIT(0);
        }
        __syncthreads();

        const uint32_t stb = sb + (uint32_t)(AST0 + st * ASTAGE) * 2;
        const int kbase = kb * 64;

        /* ---- S = Q K^T (3 products) ---- */
        float sacc[8][4];
#pragma unroll
        for (int j = 0; j < 8; j++)
#pragma unroll
            for (int i = 0; i < 4; i++) sacc[j][i] = 0.f;

#pragma unroll
        for (int kk = 0; kk < 8; kk++) {
            uint32_t qh[4], ql[4];
            const uint32_t qoff = sb + qrow_off + kk * 32;
            ldsm4(qh, qoff);
            ldsm4(ql, qoff + AQ_L * 2);
#pragma unroll
            for (int nb = 0; nb < 4; nb++) {
                uint32_t kh[4], kl[4];
                const uint32_t koff = stb + krow_off +
                    (uint32_t)(nb * 16 * AT_PAD) * 2 + kk * 32;
                ldsm4(kh, koff);
                ldsm4(kl, koff + AMAT * 2);
                mma16816(sacc[2 * nb],     qh, kh);
                mma16816(sacc[2 * nb],     qh, kl);
                mma16816(sacc[2 * nb],     ql, kh);
                mma16816(sacc[2 * nb + 1], qh, &kh[2]);
                mma16816(sacc[2 * nb + 1], qh, &kl[2]);
                mma16816(sacc[2 * nb + 1], ql, &kh[2]);
            }
        }

        /* ---- mask ---- */
#pragma unroll
        for (int j = 0; j < 8; j++) {
            const int kg0 = kbase + 8 * j + 2 * (lane & 3);
            const int kg1 = kg0 + 1;
            if (!(kg0 <= qg0 && qg0 - kg0 < WINDOW_)) sacc[j][0] = -1e30f;
            if (!(kg1 <= qg0 && qg0 - kg1 < WINDOW_)) sacc[j][1] = -1e30f;
            if (!(kg0 <= qg1 && qg1 - kg0 < WINDOW_)) sacc[j][2] = -1e30f;
            if (!(kg1 <= qg1 && qg1 - kg1 < WINDOW_)) sacc[j][3] = -1e30f;
        }

        /* ---- online softmax ---- */
        float mx0 = m0, mx1 = m1;
#pragma unroll
        for (int j = 0; j < 8; j++) {
            mx0 = fmaxf(mx0, fmaxf(sacc[j][0], sacc[j][1]));
            mx1 = fmaxf(mx1, fmaxf(sacc[j][2], sacc[j][3]));
        }
        mx0 = fmaxf(mx0, __shfl_xor_sync(0xffffffffu, mx0, 1));
        mx0 = fmaxf(mx0, __shfl_xor_sync(0xffffffffu, mx0, 2));
        mx1 = fmaxf(mx1, __shfl_xor_sync(0xffffffffu, mx1, 1));
        mx1 = fmaxf(mx1, __shfl_xor_sync(0xffffffffu, mx1, 2));

        const float sc0 = ex2f((m0 - mx0) * LOG2E);
        const float sc1 = ex2f((m1 - mx1) * LOG2E);
        float la0 = 0.f, la1 = 0.f;
#pragma unroll
        for (int j = 0; j < 8; j++) {
            float p0 = (sacc[j][0] > -1e29f) ? ex2f((sacc[j][0] - mx0) * LOG2E) : 0.f;
            float p1 = (sacc[j][1] > -1e29f) ? ex2f((sacc[j][1] - mx0) * LOG2E) : 0.f;
            float p2 = (sacc[j][2] > -1e29f) ? ex2f((sacc[j][2] - mx1) * LOG2E) : 0.f;
            float p3 = (sacc[j][3] > -1e29f) ? ex2f((sacc[j][3] - mx1) * LOG2E) : 0.f;
            sacc[j][0] = p0; sacc[j][1] = p1; sacc[j][2] = p2; sacc[j][3] = p3;
            la0 += p0 + p1;
            la1 += p2 + p3;
        }
        la0 += __shfl_xor_sync(0xffffffffu, la0, 1);
        la0 += __shfl_xor_sync(0xffffffffu, la0, 2);
        la1 += __shfl_xor_sync(0xffffffffu, la1, 1);
        la1 += __shfl_xor_sync(0xffffffffu, la1, 2);
        l0 = l0 * sc0 + la0;
        l1 = l1 * sc1 + la1;
        m0 = mx0; m1 = mx1;

#pragma unroll
        for (int nf = 0; nf < 16; nf++) {
            oacc[nf][0] *= sc0; oacc[nf][1] *= sc0;
            oacc[nf][2] *= sc1; oacc[nf][3] *= sc1;
        }

        /* ---- O += P V (3 products) ---- */
#pragma unroll
        for (int s4 = 0; s4 < 4; s4++) {
            uint32_t ah[4], al[4];
            pack_hilo(sacc[2 * s4][0],     sacc[2 * s4][1],     ah[0], al[0]);
            pack_hilo(sacc[2 * s4][2],     sacc[2 * s4][3],     ah[1], al[1]);
            pack_hilo(sacc[2 * s4 + 1][0], sacc[2 * s4 + 1][1], ah[2], al[2]);
            pack_hilo(sacc[2 * s4 + 1][2], sacc[2 * s4 + 1][3], ah[3], al[3]);

            const uint32_t vbase = stb + 2 * AMAT * 2 + vrow_off +
                                   (uint32_t)(s4 * 16 * AT_PAD) * 2;
#pragma unroll
            for (int db = 0; db < 8; db++) {
                uint32_t vh[4], vl[4];
                const uint32_t voff = vbase + db * 32;
                ldsm4t(vh, voff);
                ldsm4t(vl, voff + AMAT * 2);
                mma16816(oacc[2 * db],     ah, vh);
                mma16816(oacc[2 * db],     ah, vl);
                mma16816(oacc[2 * db],     al, vh);
                mma16816(oacc[2 * db + 1], ah, &vh[2]);
                mma16816(oacc[2 * db + 1], ah, &vl[2]);
                mma16816(oacc[2 * db + 1], al, &vh[2]);
            }
        }
        __syncthreads();
    }
#undef LOAD_KV

    /* ---- normalize + write ---- */
    const float inv0 = 1.f / l0;
    const float inv1 = 1.f / l1;
    float* O0 = g_attn + (size_t)(b * S_ + qg0) * (NH_ * D_) + h * D_;
    float* O1 = g_attn + (size_t)(b * S_ + qg1) * (NH_ * D_) + h * D_;
#pragma unroll
    for (int nf = 0; nf < 16; nf++) {
        const int dc = 8 * nf + 2 * (lane & 3);
        float2 v0 = {oacc[nf][0] * inv0, oacc[nf][1] * inv0};
        float2 v1 = {oacc[nf][2] * inv1, oacc[nf][3] * inv1};
        *(float2*)(O0 + dc) = v0;
        *(float2*)(O1 + dc) = v1;
    }
}

/* --------------------------------- launch --------------------------------- */
extern "C" void kernel_launch(void* const* d_in, const int* in_sizes, int n_in,
                              void* d_out, int out_size)
{
    const float* hidden = (const float*)d_in[0];
    const float* cosp   = (const float*)d_in[1];
    const float* sinp   = (const float*)d_in[2];
    const float* w_qkv  = (const float*)d_in[3];
    const float* b_qkv  = (const float*)d_in[4];
    const float* w_o    = (const float*)d_in[5];
    const float* b_o    = (const float*)d_in[6];
    float* out = (float*)d_out;

    float *p_qkv, *p_attn;
    __nv_bfloat16 *p_h_hi, *p_h_lo, *p_wq_hi, *p_wq_lo, *p_wo_hi, *p_wo_lo,
                  *p_at_hi, *p_at_lo;
    cudaGetSymbolAddress((void**)&p_qkv, g_qkv);
    cudaGetSymbolAddress((void**)&p_attn, g_attn);
    cudaGetSymbolAddress((void**)&p_h_hi, g_h_hi);
    cudaGetSymbolAddress((void**)&p_h_lo, g_h_lo);
    cudaGetSymbolAddress((void**)&p_wq_hi, g_wq_hi);
    cudaGetSymbolAddress((void**)&p_wq_lo, g_wq_lo);
    cudaGetSymbolAddress((void**)&p_wo_hi, g_wo_hi);
    cudaGetSymbolAddress((void**)&p_wo_lo, g_wo_lo);
    cudaGetSymbolAddress((void**)&p_at_hi, g_at_hi);
    cudaGetSymbolAddress((void**)&p_at_lo, g_at_lo);

    cudaFuncSetAttribute(gemm_mma_bf16x3,
                         cudaFuncAttributeMaxDynamicSharedMemorySize, GSMEM);
    cudaFuncSetAttribute(attn_mma,
                         cudaFuncAttributeMaxDynamicSharedMemorySize, ATTN_SMEM_B);

    /* converts */
    cvt_split<<<(BS_ * HID_ / 4 + 255) / 256, 256>>>(hidden, p_h_hi, p_h_lo,
                                                     BS_ * HID_ / 4);
    cvt_split<<<(QKV_OUT_ * HID_ / 4 + 255) / 256, 256>>>(w_qkv, p_wq_hi, p_wq_lo,
                                                          QKV_OUT_ * HID_ / 4);
    cvt_split<<<(HID_ * HID_ / 4 + 255) / 256, 256>>>(w_o, p_wo_hi, p_wo_lo,
                                                      HID_ * HID_ / 4);

    /* 1) qkv = hidden @ w_qkv^T + b_qkv */
    gemm_mma_bf16x3<<<dim3(QKV_OUT_ / 128, BS_ / 128), 512, GSMEM>>>(
        p_h_hi, p_h_lo, p_wq_hi, p_wq_lo, b_qkv, p_qkv, QKV_OUT_, HID_);

    /* 2) RoPE + split to bf16 hi/lo */
    rope_split_kernel<<<(BS_ * QKV_OUT_ + 255) / 256, 256>>>(cosp, sinp);

    /* 3) HMMA flash attention */
    attn_mma<<<dim3(S_ / 128, NH_, B_), 256, ATTN_SMEM_B>>>();

    /* 4) convert attn, then out = attn @ w_o^T + b_o */
    cvt_split<<<(BS_ * HID_ / 4 + 255) / 256, 256>>>(p_attn, p_at_hi, p_at_lo,
                                                     BS_ * HID_ / 4);
    gemm_mma_bf16x3<<<dim3(HID_ / 128, BS_ / 128), 512, GSMEM>>>(
        p_at_hi, p_at_lo, p_wo_hi, p_wo_lo, b_o, out, HID_, HID_);
}

// round 5
// speedup vs baseline: 2.5770x; 1.0112x over previous
#include <cuda_runtime.h>
#include <cuda_bf16.h>
#include <cstdint>
#include <math.h>

#define B_ 2
#define S_ 1024
#define HID_ 4096
#define NH_ 32
#define NKV_ 8
#define D_ 128
#define WINDOW_ 512
#define QKV_OUT_ ((NH_ + 2 * NKV_) * D_)   /* 6144 */
#define BS_ (B_ * S_)                      /* 2048 */

/* ------------------------- scratch (static device globals) ---------------- */
__device__ float g_qkv[BS_ * QKV_OUT_];

__device__ __nv_bfloat16 g_qh[B_ * NH_ * S_ * D_];
__device__ __nv_bfloat16 g_ql[B_ * NH_ * S_ * D_];
__device__ __nv_bfloat16 g_kh[B_ * NKV_ * S_ * D_];
__device__ __nv_bfloat16 g_kl[B_ * NKV_ * S_ * D_];
__device__ __nv_bfloat16 g_vh[B_ * NKV_ * S_ * D_];
__device__ __nv_bfloat16 g_vl[B_ * NKV_ * S_ * D_];

__device__ __nv_bfloat16 g_h_hi[BS_ * HID_];
__device__ __nv_bfloat16 g_h_lo[BS_ * HID_];
__device__ __nv_bfloat16 g_wq_hi[QKV_OUT_ * HID_];
__device__ __nv_bfloat16 g_wq_lo[QKV_OUT_ * HID_];
__device__ __nv_bfloat16 g_wo_hi[HID_ * HID_];
__device__ __nv_bfloat16 g_wo_lo[HID_ * HID_];
__device__ __nv_bfloat16 g_at_hi[BS_ * HID_];
__device__ __nv_bfloat16 g_at_lo[BS_ * HID_];

/* ============================ PTX helpers (base ISA only) ================= */
__device__ __forceinline__ uint32_t smem_u32(const void* p) {
    return (uint32_t)__cvta_generic_to_shared(p);
}
__device__ __forceinline__ void cp_async16(uint32_t dst, const void* src) {
    asm volatile("cp.async.cg.shared.global [%0], [%1], 16;\n"
                 :: "r"(dst), "l"(src));
}
#define CP_COMMIT() asm volatile("cp.async.commit_group;\n" ::: "memory")
#define CP_WAIT(n)  asm volatile("cp.async.wait_group %0;\n" :: "n"(n) : "memory")

__device__ __forceinline__ void ldsm4(uint32_t* r, uint32_t addr) {
    asm volatile("ldmatrix.sync.aligned.m8n8.x4.shared.b16 {%0,%1,%2,%3}, [%4];"
                 : "=r"(r[0]), "=r"(r[1]), "=r"(r[2]), "=r"(r[3]) : "r"(addr));
}
__device__ __forceinline__ void ldsm4t(uint32_t* r, uint32_t addr) {
    asm volatile("ldmatrix.sync.aligned.m8n8.x4.trans.shared.b16 {%0,%1,%2,%3}, [%4];"
                 : "=r"(r[0]), "=r"(r[1]), "=r"(r[2]), "=r"(r[3]) : "r"(addr));
}
__device__ __forceinline__ void mma16816(float* d, const uint32_t* a,
                                         const uint32_t* b) {
    asm volatile("mma.sync.aligned.m16n8k16.row.col.f32.bf16.bf16.f32 "
                 "{%0,%1,%2,%3}, {%4,%5,%6,%7}, {%8,%9}, {%0,%1,%2,%3};"
                 : "+f"(d[0]), "+f"(d[1]), "+f"(d[2]), "+f"(d[3])
                 : "r"(a[0]), "r"(a[1]), "r"(a[2]), "r"(a[3]),
                   "r"(b[0]), "r"(b[1]));
}
__device__ __forceinline__ float ex2f(float x) {
    float y;
    asm("ex2.approx.f32 %0, %1;" : "=f"(y) : "f"(x));
    return y;
}
__device__ __forceinline__ void pack_hilo(float x, float y,
                                          uint32_t& hw, uint32_t& lw) {
    __nv_bfloat162 h = __float22bfloat162_rn(make_float2(x, y));
    float2 hf = __bfloat1622float2(h);
    __nv_bfloat162 l = __float22bfloat162_rn(make_float2(x - hf.x, y - hf.y));
    hw = *(uint32_t*)&h;
    lw = *(uint32_t*)&l;
}

/* ==================== fp32 -> bf16 hi/lo split ============================ */
__global__ void cvt_split(const float* __restrict__ x,
                          __nv_bfloat16* __restrict__ hi,
                          __nv_bfloat16* __restrict__ lo, int n4)
{
    int i = blockIdx.x * blockDim.x + threadIdx.x;
    if (i >= n4) return;
    float4 v = ((const float4*)x)[i];
    __nv_bfloat16 h0 = __float2bfloat16(v.x);
    __nv_bfloat16 h1 = __float2bfloat16(v.y);
    __nv_bfloat16 h2 = __float2bfloat16(v.z);
    __nv_bfloat16 h3 = __float2bfloat16(v.w);
    __nv_bfloat16 l0 = __float2bfloat16(v.x - __bfloat162float(h0));
    __nv_bfloat16 l1 = __float2bfloat16(v.y - __bfloat162float(h1));
    __nv_bfloat16 l2 = __float2bfloat16(v.z - __bfloat162float(h2));
    __nv_bfloat16 l3 = __float2bfloat16(v.w - __bfloat162float(h3));
    __nv_bfloat162 hv0 = {h0, h1}, hv1 = {h2, h3};
    __nv_bfloat162 lv0 = {l0, l1}, lv1 = {l2, l3};
    uint2 hw, lw;
    hw.x = *(uint32_t*)&hv0; hw.y = *(uint32_t*)&hv1;
    lw.x = *(uint32_t*)&lv0; lw.y = *(uint32_t*)&lv1;
    ((uint2*)hi)[i] = hw;
    ((uint2*)lo)[i] = lw;
}

/* ============== HMMA GEMM: C = A*B^T + bias, 3xBF16 split ================= */
/* 4-stage cp.async ring, ONE __syncthreads per K-iteration.                  */
#define GTILE (128 * 40)
#define GSTAGE_B (4 * GTILE * 2)          /* 40960 B per stage */
#define GSTAGES 4
#define GSMEM (GSTAGES * GSTAGE_B)        /* 163840 B */

__global__ void __launch_bounds__(512) gemm_mma_bf16x3(
    const __nv_bfloat16* __restrict__ Ah, const __nv_bfloat16* __restrict__ Al,
    const __nv_bfloat16* __restrict__ Bh, const __nv_bfloat16* __restrict__ Bl,
    const float* __restrict__ bias, float* __restrict__ C, int N, int K)
{
    extern __shared__ __nv_bfloat16 smem[];
    const uint32_t sb = smem_u32(smem);

    const int tid  = threadIdx.x;
    const int lane = tid & 31;
    const int wid  = tid >> 5;
    const int wy   = wid >> 2;
    const int wx   = wid & 3;
    const int m0   = blockIdx.y * 128;
    const int n0   = blockIdx.x * 128;
    const int KT   = K / 32;

    const int lr = tid >> 2;
    const int lc = (tid & 3) * 8;
    const uint32_t doff = (uint32_t)(lr * 40 + lc) * 2;

    float acc[2][4][4];
#pragma unroll
    for (int mt = 0; mt < 2; mt++)
#pragma unroll
        for (int nt = 0; nt < 4; nt++)
#pragma unroll
            for (int j = 0; j < 4; j++) acc[mt][nt][j] = 0.f;

    const int a_row = wy * 32 + (lane & 15);
    const int a_col = (lane >> 4) * 8;
    const uint32_t a_off = (uint32_t)(a_row * 40 + a_col) * 2;
    const int b_row = wx * 32 + ((lane >> 4) << 3) + (lane & 7);
    const int b_col = ((lane >> 3) & 1) * 8;
    const uint32_t b_off = (uint32_t)(b_row * 40 + b_col) * 2;

#define LOAD_STAGE(kt, st) do {                                         \
        const int k0_ = (kt) * 32;                                      \
        const uint32_t s0_ = sb + (st) * GSTAGE_B + doff;               \
        const size_t asrc_ = (size_t)(m0 + lr) * K + k0_ + lc;          \
        const size_t bsrc_ = (size_t)(n0 + lr) * K + k0_ + lc;          \
        cp_async16(s0_ + 0 * GTILE * 2, Ah + asrc_);                    \
        cp_async16(s0_ + 1 * GTILE * 2, Al + asrc_);                    \
        cp_async16(s0_ + 2 * GTILE * 2, Bh + bsrc_);                    \
        cp_async16(s0_ + 3 * GTILE * 2, Bl + bsrc_);                    \
    } while (0)

    /* prologue: stages 0..2 */
#pragma unroll
    for (int s = 0; s < GSTAGES - 1; s++) {
        LOAD_STAGE(s, s);
        CP_COMMIT();
    }

    for (int kt = 0; kt < KT; kt++) {
        CP_WAIT(GSTAGES - 2);              /* stage kt resident          */
        __syncthreads();                   /* visible + slot kt-1 free   */
        if (kt + GSTAGES - 1 < KT) {
            LOAD_STAGE(kt + GSTAGES - 1, (kt + GSTAGES - 1) & (GSTAGES - 1));
            CP_COMMIT();
        }

        const uint32_t stb = sb + (kt & (GSTAGES - 1)) * GSTAGE_B;
#pragma unroll
        for (int ks = 0; ks < 32; ks += 16) {
            const uint32_t kso = (uint32_t)ks * 2;
            uint32_t ah[2][4], al[2][4], bh[4][2], bl[4][2];
#pragma unroll
            for (int mt = 0; mt < 2; mt++) {
                uint32_t ao = stb + a_off + (uint32_t)(mt * 16 * 40) * 2 + kso;
                ldsm4(ah[mt], ao);
                ldsm4(al[mt], ao + GTILE * 2);
            }
#pragma unroll
            for (int nt2 = 0; nt2 < 2; nt2++) {
                uint32_t bo = stb + 2 * GTILE * 2 + b_off +
                              (uint32_t)(nt2 * 16 * 40) * 2 + kso;
                uint32_t r[4];
                ldsm4(r, bo);
                bh[nt2 * 2][0] = r[0]; bh[nt2 * 2][1] = r[1];
                bh[nt2 * 2 + 1][0] = r[2]; bh[nt2 * 2 + 1][1] = r[3];
                ldsm4(r, bo + GTILE * 2);
                bl[nt2 * 2][0] = r[0]; bl[nt2 * 2][1] = r[1];
                bl[nt2 * 2 + 1][0] = r[2]; bl[nt2 * 2 + 1][1] = r[3];
            }
#pragma unroll
            for (int mt = 0; mt < 2; mt++)
#pragma unroll
                for (int nt = 0; nt < 4; nt++)
                    mma16816(acc[mt][nt], ah[mt], bh[nt]);
#pragma unroll
            for (int mt = 0; mt < 2; mt++)
#pragma unroll
                for (int nt = 0; nt < 4; nt++)
                    mma16816(acc[mt][nt], ah[mt], bl[nt]);
#pragma unroll
            for (int mt = 0; mt < 2; mt++)
#pragma unroll
                for (int nt = 0; nt < 4; nt++)
                    mma16816(acc[mt][nt], al[mt], bh[nt]);
        }
    }
#undef LOAD_STAGE

#pragma unroll
    for (int mt = 0; mt < 2; mt++) {
        int row0 = m0 + wy * 32 + mt * 16 + (lane >> 2);
#pragma unroll
        for (int nt = 0; nt < 4; nt++) {
            int col = n0 + wx * 32 + nt * 8 + (lane & 3) * 2;
            float b0 = bias[col], b1 = bias[col + 1];
            float2 v0 = {acc[mt][nt][0] + b0, acc[mt][nt][1] + b1};
            float2 v1 = {acc[mt][nt][2] + b0, acc[mt][nt][3] + b1};
            *(float2*)(C + (size_t)row0 * N + col)       = v0;
            *(float2*)(C + (size_t)(row0 + 8) * N + col) = v1;
        }
    }
}

/* -------- RoPE + split qkv into bf16 hi/lo attention layouts -------------- */
__global__ void rope_split_kernel(const float* __restrict__ cosp,
                                  const float* __restrict__ sinp)
{
    int idx = blockIdx.x * blockDim.x + threadIdx.x;
    if (idx >= BS_ * QKV_OUT_) return;
    int col = idx % QKV_OUT_;
    int bs  = idx / QKV_OUT_;
    int b   = bs / S_;
    int s   = bs - b * S_;
    int d   = col & (D_ - 1);
    float v = g_qkv[idx];
    const float SCALE = 0.08838834764831845f;  /* 1/sqrt(128) */

    float val;
    size_t dst;
    __nv_bfloat16 *ph, *pl;
    if (col < NH_ * D_) {
        int h = col >> 7;
        float c  = cosp[s * D_ + d];
        float sn = sinp[s * D_ + d];
        float partner = g_qkv[(size_t)bs * QKV_OUT_ + (col ^ 64)];
        float r = (d < 64) ? -partner : partner;
        val = (v * c + r * sn) * SCALE;
        dst = (((size_t)b * NH_ + h) * S_ + s) * D_ + d;
        ph = g_qh; pl = g_ql;
    } else if (col < (NH_ + NKV_) * D_) {
        int kvh = (col - NH_ * D_) >> 7;
        float c  = cosp[s * D_ + d];
        float sn = sinp[s * D_ + d];
        float partner = g_qkv[(size_t)bs * QKV_OUT_ + (col ^ 64)];
        float r = (d < 64) ? -partner : partner;
        val = v * c + r * sn;
        dst = (((size_t)b * NKV_ + kvh) * S_ + s) * D_ + d;
        ph = g_kh; pl = g_kl;
    } else {
        int kvh = (col - (NH_ + NKV_) * D_) >> 7;
        val = v;
        dst = (((size_t)b * NKV_ + kvh) * S_ + s) * D_ + d;
        ph = g_vh; pl = g_vl;
    }
    __nv_bfloat16 hv = __float2bfloat16(val);
    ph[dst] = hv;
    pl[dst] = __float2bfloat16(val - __bfloat162float(hv));
}

/* ============ HMMA flash attention (sliding window, GQA) ================== */
#define AT_PAD 136
#define AQ_L   (128 * AT_PAD)
#define AST0   (2 * 128 * AT_PAD)
#define AMAT   (64 * AT_PAD)
#define ASTAGE (4 * AMAT)
#define ATTN_SMEM_B ((AST0 + 2 * ASTAGE) * 2)
#define LOG2E 1.4426950408889634f

__global__ void __launch_bounds__(256, 1) attn_mma()
{
    const int qbx = blockIdx.x, h = blockIdx.y, b = blockIdx.z;
    const int kvh = h >> 2;
    const int qlo = qbx * 128;

    extern __shared__ __nv_bfloat16 asmem[];
    const uint32_t sb = smem_u32(asmem);
    const int tid = threadIdx.x, lane = tid & 31, w = tid >> 5;

    const __nv_bfloat16* Qhg = g_qh + (((size_t)b * NH_ + h) * S_ + qlo) * D_;
    const __nv_bfloat16* Qlg = g_ql + (((size_t)b * NH_ + h) * S_ + qlo) * D_;
    const __nv_bfloat16* Khg = g_kh + ((size_t)b * NKV_ + kvh) * S_ * D_;
    const __nv_bfloat16* Klg = g_kl + ((size_t)b * NKV_ + kvh) * S_ * D_;
    const __nv_bfloat16* Vhg = g_vh + ((size_t)b * NKV_ + kvh) * S_ * D_;
    const __nv_bfloat16* Vlg = g_vl + ((size_t)b * NKV_ + kvh) * S_ * D_;

    for (int c = tid; c < 2048; c += 256) {
        int row = c >> 4, ch = c & 15;
        uint32_t dq = sb + (uint32_t)(row * AT_PAD + ch * 8) * 2;
        size_t src = (size_t)row * D_ + ch * 8;
        cp_async16(dq, Qhg + src);
        cp_async16(dq + AQ_L * 2, Qlg + src);
    }

#define LOAD_KV(kb, st) do {                                            \
        const int kbase_ = (kb) * 64;                                   \
        const uint32_t s0_ = sb + (uint32_t)(AST0 + (st) * ASTAGE) * 2; \
        for (int c = tid; c < 1024; c += 256) {                         \
            int row_ = c >> 4, ch_ = c & 15;                            \
            uint32_t d_ = s0_ + (uint32_t)(row_ * AT_PAD + ch_ * 8) * 2;\
            size_t src_ = (size_t)(kbase_ + row_) * D_ + ch_ * 8;       \
            cp_async16(d_,                Khg + src_);                  \
            cp_async16(d_ + AMAT * 2,     Klg + src_);                  \
            cp_async16(d_ + 2 * AMAT * 2, Vhg + src_);                  \
            cp_async16(d_ + 3 * AMAT * 2, Vlg + src_);                  \
        } } while (0)

    int kstart = qlo - (WINDOW_ - 1);
    if (kstart < 0) kstart = 0;
    const int kb0 = kstart >> 6;
    const int kb1 = (qlo + 127) >> 6;

    LOAD_KV(kb0, 0);
    CP_COMMIT();

    float oacc[16][4];
#pragma unroll
    for (int nf = 0; nf < 16; nf++)
#pragma unroll
        for (int j = 0; j < 4; j++) oacc[nf][j] = 0.f;
    float m0 = -1e30f, m1 = -1e30f, l0 = 0.f, l1 = 0.f;

    const int qg0 = qlo + w * 16 + (lane >> 2);
    const int qg1 = qg0 + 8;
    const uint32_t qrow_off =
        (uint32_t)((w * 16 + (lane & 15)) * AT_PAD + (lane >> 4) * 8) * 2;
    const uint32_t krow_off =
        (uint32_t)((((lane >> 4) << 3) + (lane & 7)) * AT_PAD +
                   ((lane >> 3) & 1) * 8) * 2;
    const uint32_t vrow_off =
        (uint32_t)((lane & 15) * AT_PAD + (lane >> 4) * 8) * 2;

    for (int kb = kb0; kb <= kb1; kb++) {
        const int st = (kb - kb0) & 1;
        if (kb < kb1) {
            LOAD_KV(kb + 1, st ^ 1);
            CP_COMMIT();
            CP_WAIT(1);
        } else {
            CP_WAIT(0);
        }
        __syncthreads();

        const uint32_t stb = sb + (uint32_t)(AST0 + st * ASTAGE) * 2;
        const int kbase = kb * 64;

        float sacc[8][4];
#pragma unroll
        for (int j = 0; j < 8; j++)
#pragma unroll
            for (int i = 0; i < 4; i++) sacc[j][i] = 0.f;

#pragma unroll
        for (int kk = 0; kk < 8; kk++) {
            uint32_t qh[4], ql[4];
            const uint32_t qoff = sb + qrow_off + kk * 32;
            ldsm4(qh, qoff);
            ldsm4(ql, qoff + AQ_L * 2);
#pragma unroll
            for (int nb = 0; nb < 4; nb++) {
                uint32_t kh[4], kl[4];
                const uint32_t koff = stb + krow_off +
                    (uint32_t)(nb * 16 * AT_PAD) * 2 + kk * 32;
                ldsm4(kh, koff);
                ldsm4(kl, koff + AMAT * 2);
                mma16816(sacc[2 * nb],     qh, kh);
                mma16816(sacc[2 * nb],     qh, kl);
                mma16816(sacc[2 * nb],     ql, kh);
                mma16816(sacc[2 * nb + 1], qh, &kh[2]);
                mma16816(sacc[2 * nb + 1], qh, &kl[2]);
                mma16816(sacc[2 * nb + 1], ql, &kh[2]);
            }
        }

#pragma unroll
        for (int j = 0; j < 8; j++) {
            const int kg0 = kbase + 8 * j + 2 * (lane & 3);
            const int kg1 = kg0 + 1;
            if (!(kg0 <= qg0 && qg0 - kg0 < WINDOW_)) sacc[j][0] = -1e30f;
            if (!(kg1 <= qg0 && qg0 - kg1 < WINDOW_)) sacc[j][1] = -1e30f;
            if (!(kg0 <= qg1 && qg1 - kg0 < WINDOW_)) sacc[j][2] = -1e30f;
            if (!(kg1 <= qg1 && qg1 - kg1 < WINDOW_)) sacc[j][3] = -1e30f;
        }

        float mx0 = m0, mx1 = m1;
#pragma unroll
        for (int j = 0; j < 8; j++) {
            mx0 = fmaxf(mx0, fmaxf(sacc[j][0], sacc[j][1]));
            mx1 = fmaxf(mx1, fmaxf(sacc[j][2], sacc[j][3]));
        }
        mx0 = fmaxf(mx0, __shfl_xor_sync(0xffffffffu, mx0, 1));
        mx0 = fmaxf(mx0, __shfl_xor_sync(0xffffffffu, mx0, 2));
        mx1 = fmaxf(mx1, __shfl_xor_sync(0xffffffffu, mx1, 1));
        mx1 = fmaxf(mx1, __shfl_xor_sync(0xffffffffu, mx1, 2));

        const float sc0 = ex2f((m0 - mx0) * LOG2E);
        const float sc1 = ex2f((m1 - mx1) * LOG2E);
        float la0 = 0.f, la1 = 0.f;
#pragma unroll
        for (int j = 0; j < 8; j++) {
            float p0 = (sacc[j][0] > -1e29f) ? ex2f((sacc[j][0] - mx0) * LOG2E) : 0.f;
            float p1 = (sacc[j][1] > -1e29f) ? ex2f((sacc[j][1] - mx0) * LOG2E) : 0.f;
            float p2 = (sacc[j][2] > -1e29f) ? ex2f((sacc[j][2] - mx1) * LOG2E) : 0.f;
            float p3 = (sacc[j][3] > -1e29f) ? ex2f((sacc[j][3] - mx1) * LOG2E) : 0.f;
            sacc[j][0] = p0; sacc[j][1] = p1; sacc[j][2] = p2; sacc[j][3] = p3;
            la0 += p0 + p1;
            la1 += p2 + p3;
        }
        la0 += __shfl_xor_sync(0xffffffffu, la0, 1);
        la0 += __shfl_xor_sync(0xffffffffu, la0, 2);
        la1 += __shfl_xor_sync(0xffffffffu, la1, 1);
        la1 += __shfl_xor_sync(0xffffffffu, la1, 2);
        l0 = l0 * sc0 + la0;
        l1 = l1 * sc1 + la1;
        m0 = mx0; m1 = mx1;

#pragma unroll
        for (int nf = 0; nf < 16; nf++) {
            oacc[nf][0] *= sc0; oacc[nf][1] *= sc0;
            oacc[nf][2] *= sc1; oacc[nf][3] *= sc1;
        }

#pragma unroll
        for (int s4 = 0; s4 < 4; s4++) {
            uint32_t ah[4], al[4];
            pack_hilo(sacc[2 * s4][0],     sacc[2 * s4][1],     ah[0], al[0]);
            pack_hilo(sacc[2 * s4][2],     sacc[2 * s4][3],     ah[1], al[1]);
            pack_hilo(sacc[2 * s4 + 1][0], sacc[2 * s4 + 1][1], ah[2], al[2]);
            pack_hilo(sacc[2 * s4 + 1][2], sacc[2 * s4 + 1][3], ah[3], al[3]);

            const uint32_t vbase = stb + 2 * AMAT * 2 + vrow_off +
                                   (uint32_t)(s4 * 16 * AT_PAD) * 2;
#pragma unroll
            for (int db = 0; db < 8; db++) {
                uint32_t vh[4], vl[4];
                const uint32_t voff = vbase + db * 32;
                ldsm4t(vh, voff);
                ldsm4t(vl, voff + AMAT * 2);
                mma16816(oacc[2 * db],     ah, vh);
                mma16816(oacc[2 * db],     ah, vl);
                mma16816(oacc[2 * db],     al, vh);
                mma16816(oacc[2 * db + 1], ah, &vh[2]);
                mma16816(oacc[2 * db + 1], ah, &vl[2]);
                mma16816(oacc[2 * db + 1], al, &vh[2]);
            }
        }
        __syncthreads();
    }
#undef LOAD_KV

    /* ---- normalize + write directly as bf16 hi/lo -------------------- */
    const float inv0 = 1.f / l0;
    const float inv1 = 1.f / l1;
    const size_t o0 = (size_t)(b * S_ + qg0) * (NH_ * D_) + h * D_;
    const size_t o1 = (size_t)(b * S_ + qg1) * (NH_ * D_) + h * D_;
#pragma unroll
    for (int nf = 0; nf < 16; nf++) {
        const int dc = 8 * nf + 2 * (lane & 3);
        uint32_t hw, lw;
        pack_hilo(oacc[nf][0] * inv0, oacc[nf][1] * inv0, hw, lw);
        *(uint32_t*)(g_at_hi + o0 + dc) = hw;
        *(uint32_t*)(g_at_lo + o0 + dc) = lw;
        pack_hilo(oacc[nf][2] * inv1, oacc[nf][3] * inv1, hw, lw);
        *(uint32_t*)(g_at_hi + o1 + dc) = hw;
        *(uint32_t*)(g_at_lo + o1 + dc) = lw;
    }
}

/* --------------------------------- launch --------------------------------- */
extern "C" void kernel_launch(void* const* d_in, const int* in_sizes, int n_in,
                              void* d_out, int out_size)
{
    const float* hidden = (const float*)d_in[0];
    const float* cosp   = (const float*)d_in[1];
    const float* sinp   = (const float*)d_in[2];
    const float* w_qkv  = (const float*)d_in[3];
    const float* b_qkv  = (const float*)d_in[4];
    const float* w_o    = (const float*)d_in[5];
    const float* b_o    = (const float*)d_in[6];
    float* out = (float*)d_out;

    float *p_qkv;
    __nv_bfloat16 *p_h_hi, *p_h_lo, *p_wq_hi, *p_wq_lo, *p_wo_hi, *p_wo_lo,
                  *p_at_hi, *p_at_lo;
    cudaGetSymbolAddress((void**)&p_qkv, g_qkv);
    cudaGetSymbolAddress((void**)&p_h_hi, g_h_hi);
    cudaGetSymbolAddress((void**)&p_h_lo, g_h_lo);
    cudaGetSymbolAddress((void**)&p_wq_hi, g_wq_hi);
    cudaGetSymbolAddress((void**)&p_wq_lo, g_wq_lo);
    cudaGetSymbolAddress((void**)&p_wo_hi, g_wo_hi);
    cudaGetSymbolAddress((void**)&p_wo_lo, g_wo_lo);
    cudaGetSymbolAddress((void**)&p_at_hi, g_at_hi);
    cudaGetSymbolAddress((void**)&p_at_lo, g_at_lo);

    cudaFuncSetAttribute(gemm_mma_bf16x3,
                         cudaFuncAttributeMaxDynamicSharedMemorySize, GSMEM);
    cudaFuncSetAttribute(attn_mma,
                         cudaFuncAttributeMaxDynamicSharedMemorySize, ATTN_SMEM_B);

    /* converts */
    cvt_split<<<(BS_ * HID_ / 4 + 255) / 256, 256>>>(hidden, p_h_hi, p_h_lo,
                                                     BS_ * HID_ / 4);
    cvt_split<<<(QKV_OUT_ * HID_ / 4 + 255) / 256, 256>>>(w_qkv, p_wq_hi, p_wq_lo,
                                                          QKV_OUT_ * HID_ / 4);
    cvt_split<<<(HID_ * HID_ / 4 + 255) / 256, 256>>>(w_o, p_wo_hi, p_wo_lo,
                                                      HID_ * HID_ / 4);

    /* 1) qkv = hidden @ w_qkv^T + b_qkv */
    gemm_mma_bf16x3<<<dim3(QKV_OUT_ / 128, BS_ / 128), 512, GSMEM>>>(
        p_h_hi, p_h_lo, p_wq_hi, p_wq_lo, b_qkv, p_qkv, QKV_OUT_, HID_);

    /* 2) RoPE + split to bf16 hi/lo */
    rope_split_kernel<<<(BS_ * QKV_OUT_ + 255) / 256, 256>>>(cosp, sinp);

    /* 3) HMMA flash attention (writes bf16 hi/lo directly) */
    attn_mma<<<dim3(S_ / 128, NH_, B_), 256, ATTN_SMEM_B>>>();

    /* 4) out = attn @ w_o^T + b_o */
    gemm_mma_bf16x3<<<dim3(HID_ / 128, BS_ / 128), 512, GSMEM>>>(
        p_at_hi, p_at_lo, p_wo_hi, p_wo_lo, b_o, out, HID_, HID_);
}

// round 6
// speedup vs baseline: 2.9308x; 1.1373x over previous
#include <cuda_runtime.h>
#include <cuda_bf16.h>
#include <cstdint>
#include <math.h>

#define B_ 2
#define S_ 1024
#define HID_ 4096
#define NH_ 32
#define NKV_ 8
#define D_ 128
#define WINDOW_ 512
#define QKV_OUT_ ((NH_ + 2 * NKV_) * D_)   /* 6144 */
#define BS_ (B_ * S_)                      /* 2048 */

/* ------------------------- scratch (static device globals) ---------------- */
__device__ float g_qkv[BS_ * QKV_OUT_];

__device__ __nv_bfloat16 g_qh[B_ * NH_ * S_ * D_];
__device__ __nv_bfloat16 g_ql[B_ * NH_ * S_ * D_];
__device__ __nv_bfloat16 g_kh[B_ * NKV_ * S_ * D_];
__device__ __nv_bfloat16 g_kl[B_ * NKV_ * S_ * D_];
__device__ __nv_bfloat16 g_vh[B_ * NKV_ * S_ * D_];
__device__ __nv_bfloat16 g_vl[B_ * NKV_ * S_ * D_];

__device__ __nv_bfloat16 g_h_hi[BS_ * HID_];
__device__ __nv_bfloat16 g_h_lo[BS_ * HID_];
__device__ __nv_bfloat16 g_wq_hi[QKV_OUT_ * HID_];
__device__ __nv_bfloat16 g_wq_lo[QKV_OUT_ * HID_];
__device__ __nv_bfloat16 g_wo_hi[HID_ * HID_];
__device__ __nv_bfloat16 g_wo_lo[HID_ * HID_];
__device__ __nv_bfloat16 g_at_hi[BS_ * HID_];
__device__ __nv_bfloat16 g_at_lo[BS_ * HID_];

/* ============================ PTX helpers (base ISA only) ================= */
__device__ __forceinline__ uint32_t smem_u32(const void* p) {
    return (uint32_t)__cvta_generic_to_shared(p);
}
__device__ __forceinline__ void cp_async16(uint32_t dst, const void* src) {
    asm volatile("cp.async.cg.shared.global [%0], [%1], 16;\n"
                 :: "r"(dst), "l"(src));
}
#define CP_COMMIT() asm volatile("cp.async.commit_group;\n" ::: "memory")
#define CP_WAIT(n)  asm volatile("cp.async.wait_group %0;\n" :: "n"(n) : "memory")

__device__ __forceinline__ void ldsm4(uint32_t* r, uint32_t addr) {
    asm volatile("ldmatrix.sync.aligned.m8n8.x4.shared.b16 {%0,%1,%2,%3}, [%4];"
                 : "=r"(r[0]), "=r"(r[1]), "=r"(r[2]), "=r"(r[3]) : "r"(addr));
}
__device__ __forceinline__ void ldsm4t(uint32_t* r, uint32_t addr) {
    asm volatile("ldmatrix.sync.aligned.m8n8.x4.trans.shared.b16 {%0,%1,%2,%3}, [%4];"
                 : "=r"(r[0]), "=r"(r[1]), "=r"(r[2]), "=r"(r[3]) : "r"(addr));
}
__device__ __forceinline__ void mma16816(float* d, const uint32_t* a,
                                         const uint32_t* b) {
    asm volatile("mma.sync.aligned.m16n8k16.row.col.f32.bf16.bf16.f32 "
                 "{%0,%1,%2,%3}, {%4,%5,%6,%7}, {%8,%9}, {%0,%1,%2,%3};"
                 : "+f"(d[0]), "+f"(d[1]), "+f"(d[2]), "+f"(d[3])
                 : "r"(a[0]), "r"(a[1]), "r"(a[2]), "r"(a[3]),
                   "r"(b[0]), "r"(b[1]));
}
__device__ __forceinline__ float ex2f(float x) {
    float y;
    asm("ex2.approx.f32 %0, %1;" : "=f"(y) : "f"(x));
    return y;
}
__device__ __forceinline__ void pack_hilo(float x, float y,
                                          uint32_t& hw, uint32_t& lw) {
    __nv_bfloat162 h = __float22bfloat162_rn(make_float2(x, y));
    float2 hf = __bfloat1622float2(h);
    __nv_bfloat162 l = __float22bfloat162_rn(make_float2(x - hf.x, y - hf.y));
    hw = *(uint32_t*)&h;
    lw = *(uint32_t*)&l;
}

/* ==================== fp32 -> bf16 hi/lo split ============================ */
__global__ void cvt_split(const float* __restrict__ x,
                          __nv_bfloat16* __restrict__ hi,
                          __nv_bfloat16* __restrict__ lo, int n4)
{
    int i = blockIdx.x * blockDim.x + threadIdx.x;
    if (i >= n4) return;
    float4 v = ((const float4*)x)[i];
    __nv_bfloat16 h0 = __float2bfloat16(v.x);
    __nv_bfloat16 h1 = __float2bfloat16(v.y);
    __nv_bfloat16 h2 = __float2bfloat16(v.z);
    __nv_bfloat16 h3 = __float2bfloat16(v.w);
    __nv_bfloat16 l0 = __float2bfloat16(v.x - __bfloat162float(h0));
    __nv_bfloat16 l1 = __float2bfloat16(v.y - __bfloat162float(h1));
    __nv_bfloat16 l2 = __float2bfloat16(v.z - __bfloat162float(h2));
    __nv_bfloat16 l3 = __float2bfloat16(v.w - __bfloat162float(h3));
    __nv_bfloat162 hv0 = {h0, h1}, hv1 = {h2, h3};
    __nv_bfloat162 lv0 = {l0, l1}, lv1 = {l2, l3};
    uint2 hw, lw;
    hw.x = *(uint32_t*)&hv0; hw.y = *(uint32_t*)&hv1;
    lw.x = *(uint32_t*)&lv0; lw.y = *(uint32_t*)&lv1;
    ((uint2*)hi)[i] = hw;
    ((uint2*)lo)[i] = lw;
}

/* ============== HMMA GEMM: C = A*B^T + bias, 3xBF16 split ================= */
/* CTA 128x256, 8 warps (2x4 grid of 64x64 warp tiles), BK=32, 3-stage ring. */
#define SA_HI 0
#define SA_LO (128 * 40)
#define SB_HI (2 * 128 * 40)
#define SB_LO (2 * 128 * 40 + 256 * 40)
#define GSTAGE_E (2 * 128 * 40 + 2 * 256 * 40)     /* 30720 elems */
#define GSTAGE_B (GSTAGE_E * 2)                    /* 61440 B     */
#define GSTAGES 3
#define GSMEM (GSTAGES * GSTAGE_B)                 /* 184320 B    */

__global__ void __launch_bounds__(256, 1) gemm_mma_bf16x3(
    const __nv_bfloat16* __restrict__ Ah, const __nv_bfloat16* __restrict__ Al,
    const __nv_bfloat16* __restrict__ Bh, const __nv_bfloat16* __restrict__ Bl,
    const float* __restrict__ bias, float* __restrict__ C, int N, int K)
{
    extern __shared__ __nv_bfloat16 smem[];
    const uint32_t sb = smem_u32(smem);

    const int tid  = threadIdx.x;
    const int lane = tid & 31;
    const int wid  = tid >> 5;
    const int wy   = wid >> 2;          /* 0..1 : 64-row band   */
    const int wx   = wid & 3;           /* 0..3 : 64-col band   */
    const int m0   = blockIdx.y * 128;
    const int n0   = blockIdx.x * 256;
    const int KT   = K / 32;

    /* loader: thread -> (row-in-64, 16B chunk) */
    const int lr = tid >> 2;            /* 0..63 */
    const int lc = (tid & 3) * 8;       /* 0,8,16,24 */
    const uint32_t doff = (uint32_t)(lr * 40 + lc) * 2;

    float acc[4][8][4];
#pragma unroll
    for (int mt = 0; mt < 4; mt++)
#pragma unroll
        for (int nt = 0; nt < 8; nt++)
#pragma unroll
            for (int j = 0; j < 4; j++) acc[mt][nt][j] = 0.f;

    const int a_row = wy * 64 + (lane & 15);
    const int a_col = (lane >> 4) * 8;
    const uint32_t a_off = (uint32_t)(a_row * 40 + a_col) * 2;
    const int b_row = wx * 64 + ((lane >> 4) << 3) + (lane & 7);
    const int b_col = ((lane >> 3) & 1) * 8;
    const uint32_t b_off = (uint32_t)(b_row * 40 + b_col) * 2;

#define LOAD_STAGE(kt, st) do {                                           \
        const int k0_ = (kt) * 32;                                        \
        const uint32_t s0_ = sb + (st) * GSTAGE_B + doff;                 \
        _Pragma("unroll")                                                 \
        for (int p_ = 0; p_ < 2; p_++) {                                  \
            size_t asrc_ = (size_t)(m0 + p_ * 64 + lr) * K + k0_ + lc;    \
            uint32_t d_ = s0_ + (uint32_t)(p_ * 64 * 40) * 2;             \
            cp_async16(d_ + SA_HI * 2, Ah + asrc_);                       \
            cp_async16(d_ + SA_LO * 2, Al + asrc_);                       \
        }                                                                 \
        _Pragma("unroll")                                                 \
        for (int p_ = 0; p_ < 4; p_++) {                                  \
            size_t bsrc_ = (size_t)(n0 + p_ * 64 + lr) * K + k0_ + lc;    \
            uint32_t d_ = s0_ + (uint32_t)(p_ * 64 * 40) * 2;             \
            cp_async16(d_ + SB_HI * 2, Bh + bsrc_);                       \
            cp_async16(d_ + SB_LO * 2, Bl + bsrc_);                       \
        }                                                                 \
    } while (0)

    LOAD_STAGE(0, 0);
    CP_COMMIT();
    LOAD_STAGE(1, 1);
    CP_COMMIT();

    int st = 0;
    for (int kt = 0; kt < KT; kt++) {
        CP_WAIT(1);
        __syncthreads();
        if (kt + 2 < KT) {
            int st2 = st + 2; if (st2 >= GSTAGES) st2 -= GSTAGES;
            LOAD_STAGE(kt + 2, st2);
            CP_COMMIT();
        }

        const uint32_t stb = sb + st * GSTAGE_B;
#pragma unroll
        for (int ks = 0; ks < 32; ks += 16) {
            const uint32_t kso = (uint32_t)ks * 2;
            uint32_t bh[8][2], bl[8][2];
#pragma unroll
            for (int nt2 = 0; nt2 < 4; nt2++) {
                uint32_t bo = stb + b_off + (uint32_t)(nt2 * 16 * 40) * 2 + kso;
                uint32_t r[4];
                ldsm4(r, bo + SB_HI * 2);
                bh[nt2 * 2][0] = r[0]; bh[nt2 * 2][1] = r[1];
                bh[nt2 * 2 + 1][0] = r[2]; bh[nt2 * 2 + 1][1] = r[3];
                ldsm4(r, bo + SB_LO * 2);
                bl[nt2 * 2][0] = r[0]; bl[nt2 * 2][1] = r[1];
                bl[nt2 * 2 + 1][0] = r[2]; bl[nt2 * 2 + 1][1] = r[3];
            }
#pragma unroll
            for (int mt = 0; mt < 4; mt++) {
                uint32_t ah[4], al[4];
                uint32_t ao = stb + a_off + (uint32_t)(mt * 16 * 40) * 2 + kso;
                ldsm4(ah, ao + SA_HI * 2);
                ldsm4(al, ao + SA_LO * 2);
#pragma unroll
                for (int nt = 0; nt < 8; nt++)
                    mma16816(acc[mt][nt], ah, bh[nt]);
#pragma unroll
                for (int nt = 0; nt < 8; nt++)
                    mma16816(acc[mt][nt], ah, bl[nt]);
#pragma unroll
                for (int nt = 0; nt < 8; nt++)
                    mma16816(acc[mt][nt], al, bh[nt]);
            }
        }
        st++; if (st >= GSTAGES) st -= GSTAGES;
    }
#undef LOAD_STAGE

#pragma unroll
    for (int mt = 0; mt < 4; mt++) {
        int row0 = m0 + wy * 64 + mt * 16 + (lane >> 2);
#pragma unroll
        for (int nt = 0; nt < 8; nt++) {
            int col = n0 + wx * 64 + nt * 8 + (lane & 3) * 2;
            float b0 = bias[col], b1 = bias[col + 1];
            float2 v0 = {acc[mt][nt][0] + b0, acc[mt][nt][1] + b1};
            float2 v1 = {acc[mt][nt][2] + b0, acc[mt][nt][3] + b1};
            *(float2*)(C + (size_t)row0 * N + col)       = v0;
            *(float2*)(C + (size_t)(row0 + 8) * N + col) = v1;
        }
    }
}

/* -------- RoPE + split qkv into bf16 hi/lo attention layouts -------------- */
__global__ void rope_split_kernel(const float* __restrict__ cosp,
                                  const float* __restrict__ sinp)
{
    int idx = blockIdx.x * blockDim.x + threadIdx.x;
    if (idx >= BS_ * QKV_OUT_) return;
    int col = idx % QKV_OUT_;
    int bs  = idx / QKV_OUT_;
    int b   = bs / S_;
    int s   = bs - b * S_;
    int d   = col & (D_ - 1);
    float v = g_qkv[idx];
    const float SCALE = 0.08838834764831845f;  /* 1/sqrt(128) */

    float val;
    size_t dst;
    __nv_bfloat16 *ph, *pl;
    if (col < NH_ * D_) {
        int h = col >> 7;
        float c  = cosp[s * D_ + d];
        float sn = sinp[s * D_ + d];
        float partner = g_qkv[(size_t)bs * QKV_OUT_ + (col ^ 64)];
        float r = (d < 64) ? -partner : partner;
        val = (v * c + r * sn) * SCALE;
        dst = (((size_t)b * NH_ + h) * S_ + s) * D_ + d;
        ph = g_qh; pl = g_ql;
    } else if (col < (NH_ + NKV_) * D_) {
        int kvh = (col - NH_ * D_) >> 7;
        float c  = cosp[s * D_ + d];
        float sn = sinp[s * D_ + d];
        float partner = g_qkv[(size_t)bs * QKV_OUT_ + (col ^ 64)];
        float r = (d < 64) ? -partner : partner;
        val = v * c + r * sn;
        dst = (((size_t)b * NKV_ + kvh) * S_ + s) * D_ + d;
        ph = g_kh; pl = g_kl;
    } else {
        int kvh = (col - (NH_ + NKV_) * D_) >> 7;
        val = v;
        dst = (((size_t)b * NKV_ + kvh) * S_ + s) * D_ + d;
        ph = g_vh; pl = g_vl;
    }
    __nv_bfloat16 hv = __float2bfloat16(val);
    ph[dst] = hv;
    pl[dst] = __float2bfloat16(val - __bfloat162float(hv));
}

/* ============ HMMA flash attention (sliding window, GQA) ================== */
#define AT_PAD 136
#define AQ_L   (128 * AT_PAD)
#define AST0   (2 * 128 * AT_PAD)
#define AMAT   (64 * AT_PAD)
#define ASTAGE (4 * AMAT)
#define ATTN_SMEM_B ((AST0 + 2 * ASTAGE) * 2)
#define LOG2E 1.4426950408889634f

__global__ void __launch_bounds__(256, 1) attn_mma()
{
    const int qbx = blockIdx.x, h = blockIdx.y, b = blockIdx.z;
    const int kvh = h >> 2;
    const int qlo = qbx * 128;

    extern __shared__ __nv_bfloat16 asmem[];
    const uint32_t sb = smem_u32(asmem);
    const int tid = threadIdx.x, lane = tid & 31, w = tid >> 5;

    const __nv_bfloat16* Qhg = g_qh + (((size_t)b * NH_ + h) * S_ + qlo) * D_;
    const __nv_bfloat16* Qlg = g_ql + (((size_t)b * NH_ + h) * S_ + qlo) * D_;
    const __nv_bfloat16* Khg = g_kh + ((size_t)b * NKV_ + kvh) * S_ * D_;
    const __nv_bfloat16* Klg = g_kl + ((size_t)b * NKV_ + kvh) * S_ * D_;
    const __nv_bfloat16* Vhg = g_vh + ((size_t)b * NKV_ + kvh) * S_ * D_;
    const __nv_bfloat16* Vlg = g_vl + ((size_t)b * NKV_ + kvh) * S_ * D_;

    for (int c = tid; c < 2048; c += 256) {
        int row = c >> 4, ch = c & 15;
        uint32_t dq = sb + (uint32_t)(row * AT_PAD + ch * 8) * 2;
        size_t src = (size_t)row * D_ + ch * 8;
        cp_async16(dq, Qhg + src);
        cp_async16(dq + AQ_L * 2, Qlg + src);
    }

#define LOAD_KV(kb, st) do {                                            \
        const int kbase_ = (kb) * 64;                                   \
        const uint32_t s0_ = sb + (uint32_t)(AST0 + (st) * ASTAGE) * 2; \
        for (int c = tid; c < 1024; c += 256) {                         \
            int row_ = c >> 4, ch_ = c & 15;                            \
            uint32_t d_ = s0_ + (uint32_t)(row_ * AT_PAD + ch_ * 8) * 2;\
            size_t src_ = (size_t)(kbase_ + row_) * D_ + ch_ * 8;       \
            cp_async16(d_,                Khg + src_);                  \
            cp_async16(d_ + AMAT * 2,     Klg + src_);                  \
            cp_async16(d_ + 2 * AMAT * 2, Vhg + src_);                  \
            cp_async16(d_ + 3 * AMAT * 2, Vlg + src_);                  \
        } } while (0)

    int kstart = qlo - (WINDOW_ - 1);
    if (kstart < 0) kstart = 0;
    const int kb0 = kstart >> 6;
    const int kb1 = (qlo + 127) >> 6;

    LOAD_KV(kb0, 0);
    CP_COMMIT();

    float oacc[16][4];
#pragma unroll
    for (int nf = 0; nf < 16; nf++)
#pragma unroll
        for (int j = 0; j < 4; j++) oacc[nf][j] = 0.f;
    float m0 = -1e30f, m1 = -1e30f, l0 = 0.f, l1 = 0.f;

    const int qg0 = qlo + w * 16 + (lane >> 2);
    const int qg1 = qg0 + 8;
    const uint32_t qrow_off =
        (uint32_t)((w * 16 + (lane & 15)) * AT_PAD + (lane >> 4) * 8) * 2;
    const uint32_t krow_off =
        (uint32_t)((((lane >> 4) << 3) + (lane & 7)) * AT_PAD +
                   ((lane >> 3) & 1) * 8) * 2;
    const uint32_t vrow_off =
        (uint32_t)((lane & 15) * AT_PAD + (lane >> 4) * 8) * 2;

    for (int kb = kb0; kb <= kb1; kb++) {
        const int st = (kb - kb0) & 1;
        if (kb < kb1) {
            LOAD_KV(kb + 1, st ^ 1);
            CP_COMMIT();
            CP_WAIT(1);
        } else {
            CP_WAIT(0);
        }
        __syncthreads();

        const uint32_t stb = sb + (uint32_t)(AST0 + st * ASTAGE) * 2;
        const int kbase = kb * 64;

        float sacc[8][4];
#pragma unroll
        for (int j = 0; j < 8; j++)
#pragma unroll
            for (int i = 0; i < 4; i++) sacc[j][i] = 0.f;

#pragma unroll
        for (int kk = 0; kk < 8; kk++) {
            uint32_t qh[4], ql[4];
            const uint32_t qoff = sb + qrow_off + kk * 32;
            ldsm4(qh, qoff);
            ldsm4(ql, qoff + AQ_L * 2);
#pragma unroll
            for (int nb = 0; nb < 4; nb++) {
                uint32_t kh[4], kl[4];
                const uint32_t koff = stb + krow_off +
                    (uint32_t)(nb * 16 * AT_PAD) * 2 + kk * 32;
                ldsm4(kh, koff);
                ldsm4(kl, koff + AMAT * 2);
                mma16816(sacc[2 * nb],     qh, kh);
                mma16816(sacc[2 * nb],     qh, kl);
                mma16816(sacc[2 * nb],     ql, kh);
                mma16816(sacc[2 * nb + 1], qh, &kh[2]);
                mma16816(sacc[2 * nb + 1], qh, &kl[2]);
                mma16816(sacc[2 * nb + 1], ql, &kh[2]);
            }
        }

#pragma unroll
        for (int j = 0; j < 8; j++) {
            const int kg0 = kbase + 8 * j + 2 * (lane & 3);
            const int kg1 = kg0 + 1;
            if (!(kg0 <= qg0 && qg0 - kg0 < WINDOW_)) sacc[j][0] = -1e30f;
            if (!(kg1 <= qg0 && qg0 - kg1 < WINDOW_)) sacc[j][1] = -1e30f;
            if (!(kg0 <= qg1 && qg1 - kg0 < WINDOW_)) sacc[j][2] = -1e30f;
            if (!(kg1 <= qg1 && qg1 - kg1 < WINDOW_)) sacc[j][3] = -1e30f;
        }

        float mx0 = m0, mx1 = m1;
#pragma unroll
        for (int j = 0; j < 8; j++) {
            mx0 = fmaxf(mx0, fmaxf(sacc[j][0], sacc[j][1]));
            mx1 = fmaxf(mx1, fmaxf(sacc[j][2], sacc[j][3]));
        }
        mx0 = fmaxf(mx0, __shfl_xor_sync(0xffffffffu, mx0, 1));
        mx0 = fmaxf(mx0, __shfl_xor_sync(0xffffffffu, mx0, 2));
        mx1 = fmaxf(mx1, __shfl_xor_sync(0xffffffffu, mx1, 1));
        mx1 = fmaxf(mx1, __shfl_xor_sync(0xffffffffu, mx1, 2));

        const float sc0 = ex2f((m0 - mx0) * LOG2E);
        const float sc1 = ex2f((m1 - mx1) * LOG2E);
        float la0 = 0.f, la1 = 0.f;
#pragma unroll
        for (int j = 0; j < 8; j++) {
            float p0 = (sacc[j][0] > -1e29f) ? ex2f((sacc[j][0] - mx0) * LOG2E) : 0.f;
            float p1 = (sacc[j][1] > -1e29f) ? ex2f((sacc[j][1] - mx0) * LOG2E) : 0.f;
            float p2 = (sacc[j][2] > -1e29f) ? ex2f((sacc[j][2] - mx1) * LOG2E) : 0.f;
            float p3 = (sacc[j][3] > -1e29f) ? ex2f((sacc[j][3] - mx1) * LOG2E) : 0.f;
            sacc[j][0] = p0; sacc[j][1] = p1; sacc[j][2] = p2; sacc[j][3] = p3;
            la0 += p0 + p1;
            la1 += p2 + p3;
        }
        la0 += __shfl_xor_sync(0xffffffffu, la0, 1);
        la0 += __shfl_xor_sync(0xffffffffu, la0, 2);
        la1 += __shfl_xor_sync(0xffffffffu, la1, 1);
        la1 += __shfl_xor_sync(0xffffffffu, la1, 2);
        l0 = l0 * sc0 + la0;
        l1 = l1 * sc1 + la1;
        m0 = mx0; m1 = mx1;

#pragma unroll
        for (int nf = 0; nf < 16; nf++) {
            oacc[nf][0] *= sc0; oacc[nf][1] *= sc0;
            oacc[nf][2] *= sc1; oacc[nf][3] *= sc1;
        }

#pragma unroll
        for (int s4 = 0; s4 < 4; s4++) {
            uint32_t ah[4], al[4];
            pack_hilo(sacc[2 * s4][0],     sacc[2 * s4][1],     ah[0], al[0]);
            pack_hilo(sacc[2 * s4][2],     sacc[2 * s4][3],     ah[1], al[1]);
            pack_hilo(sacc[2 * s4 + 1][0], sacc[2 * s4 + 1][1], ah[2], al[2]);
            pack_hilo(sacc[2 * s4 + 1][2], sacc[2 * s4 + 1][3], ah[3], al[3]);

            const uint32_t vbase = stb + 2 * AMAT * 2 + vrow_off +
                                   (uint32_t)(s4 * 16 * AT_PAD) * 2;
#pragma unroll
            for (int db = 0; db < 8; db++) {
                uint32_t vh[4], vl[4];
                const uint32_t voff = vbase + db * 32;
                ldsm4t(vh, voff);
                ldsm4t(vl, voff + AMAT * 2);
                mma16816(oacc[2 * db],     ah, vh);
                mma16816(oacc[2 * db],     ah, vl);
                mma16816(oacc[2 * db],     al, vh);
                mma16816(oacc[2 * db + 1], ah, &vh[2]);
                mma16816(oacc[2 * db + 1], ah, &vl[2]);
                mma16816(oacc[2 * db + 1], al, &vh[2]);
            }
        }
        __syncthreads();
    }
#undef LOAD_KV

    const float inv0 = 1.f / l0;
    const float inv1 = 1.f / l1;
    const size_t o0 = (size_t)(b * S_ + qg0) * (NH_ * D_) + h * D_;
    const size_t o1 = (size_t)(b * S_ + qg1) * (NH_ * D_) + h * D_;
#pragma unroll
    for (int nf = 0; nf < 16; nf++) {
        const int dc = 8 * nf + 2 * (lane & 3);
        uint32_t hw, lw;
        pack_hilo(oacc[nf][0] * inv0, oacc[nf][1] * inv0, hw, lw);
        *(uint32_t*)(g_at_hi + o0 + dc) = hw;
        *(uint32_t*)(g_at_lo + o0 + dc) = lw;
        pack_hilo(oacc[nf][2] * inv1, oacc[nf][3] * inv1, hw, lw);
        *(uint32_t*)(g_at_hi + o1 + dc) = hw;
        *(uint32_t*)(g_at_lo + o1 + dc) = lw;
    }
}

/* --------------------------------- launch --------------------------------- */
extern "C" void kernel_launch(void* const* d_in, const int* in_sizes, int n_in,
                              void* d_out, int out_size)
{
    const float* hidden = (const float*)d_in[0];
    const float* cosp   = (const float*)d_in[1];
    const float* sinp   = (const float*)d_in[2];
    const float* w_qkv  = (const float*)d_in[3];
    const float* b_qkv  = (const float*)d_in[4];
    const float* w_o    = (const float*)d_in[5];
    const float* b_o    = (const float*)d_in[6];
    float* out = (float*)d_out;

    float *p_qkv;
    __nv_bfloat16 *p_h_hi, *p_h_lo, *p_wq_hi, *p_wq_lo, *p_wo_hi, *p_wo_lo,
                  *p_at_hi, *p_at_lo;
    cudaGetSymbolAddress((void**)&p_qkv, g_qkv);
    cudaGetSymbolAddress((void**)&p_h_hi, g_h_hi);
    cudaGetSymbolAddress((void**)&p_h_lo, g_h_lo);
    cudaGetSymbolAddress((void**)&p_wq_hi, g_wq_hi);
    cudaGetSymbolAddress((void**)&p_wq_lo, g_wq_lo);
    cudaGetSymbolAddress((void**)&p_wo_hi, g_wo_hi);
    cudaGetSymbolAddress((void**)&p_wo_lo, g_wo_lo);
    cudaGetSymbolAddress((void**)&p_at_hi, g_at_hi);
    cudaGetSymbolAddress((void**)&p_at_lo, g_at_lo);

    cudaFuncSetAttribute(gemm_mma_bf16x3,
                         cudaFuncAttributeMaxDynamicSharedMemorySize, GSMEM);
    cudaFuncSetAttribute(attn_mma,
                         cudaFuncAttributeMaxDynamicSharedMemorySize, ATTN_SMEM_B);

    /* converts */
    cvt_split<<<(BS_ * HID_ / 4 + 255) / 256, 256>>>(hidden, p_h_hi, p_h_lo,
                                                     BS_ * HID_ / 4);
    cvt_split<<<(QKV_OUT_ * HID_ / 4 + 255) / 256, 256>>>(w_qkv, p_wq_hi, p_wq_lo,
                                                          QKV_OUT_ * HID_ / 4);
    cvt_split<<<(HID_ * HID_ / 4 + 255) / 256, 256>>>(w_o, p_wo_hi, p_wo_lo,
                                                      HID_ * HID_ / 4);

    /* 1) qkv = hidden @ w_qkv^T + b_qkv */
    gemm_mma_bf16x3<<<dim3(QKV_OUT_ / 256, BS_ / 128), 256, GSMEM>>>(
        p_h_hi, p_h_lo, p_wq_hi, p_wq_lo, b_qkv, p_qkv, QKV_OUT_, HID_);

    /* 2) RoPE + split to bf16 hi/lo */
    rope_split_kernel<<<(BS_ * QKV_OUT_ + 255) / 256, 256>>>(cosp, sinp);

    /* 3) HMMA flash attention (writes bf16 hi/lo directly) */
    attn_mma<<<dim3(S_ / 128, NH_, B_), 256, ATTN_SMEM_B>>>();

    /* 4) out = attn @ w_o^T + b_o */
    gemm_mma_bf16x3<<<dim3(HID_ / 256, BS_ / 128), 256, GSMEM>>>(
        p_at_hi, p_at_lo, p_wo_hi, p_wo_lo, b_o, out, HID_, HID_);
}

// round 7
// speedup vs baseline: 2.9699x; 1.0133x over previous
#include <cuda_runtime.h>
#include <cuda_bf16.h>
#include <cstdint>
#include <math.h>

#define B_ 2
#define S_ 1024
#define HID_ 4096
#define NH_ 32
#define NKV_ 8
#define D_ 128
#define WINDOW_ 512
#define QKV_OUT_ ((NH_ + 2 * NKV_) * D_)   /* 6144 */
#define BS_ (B_ * S_)                      /* 2048 */

/* ------------------------- scratch (static device globals) ---------------- */
__device__ float g_qkv[BS_ * QKV_OUT_];

__device__ __nv_bfloat16 g_qh[B_ * NH_ * S_ * D_];
__device__ __nv_bfloat16 g_ql[B_ * NH_ * S_ * D_];
__device__ __nv_bfloat16 g_kh[B_ * NKV_ * S_ * D_];
__device__ __nv_bfloat16 g_kl[B_ * NKV_ * S_ * D_];
__device__ __nv_bfloat16 g_vh[B_ * NKV_ * S_ * D_];
__device__ __nv_bfloat16 g_vl[B_ * NKV_ * S_ * D_];

__device__ __nv_bfloat16 g_h_hi[BS_ * HID_];
__device__ __nv_bfloat16 g_h_lo[BS_ * HID_];
__device__ __nv_bfloat16 g_wq_hi[QKV_OUT_ * HID_];
__device__ __nv_bfloat16 g_wq_lo[QKV_OUT_ * HID_];
__device__ __nv_bfloat16 g_wo_hi[HID_ * HID_];
__device__ __nv_bfloat16 g_wo_lo[HID_ * HID_];
__device__ __nv_bfloat16 g_at_hi[BS_ * HID_];
__device__ __nv_bfloat16 g_at_lo[BS_ * HID_];

/* ============================ PTX helpers (base ISA only) ================= */
__device__ __forceinline__ uint32_t smem_u32(const void* p) {
    return (uint32_t)__cvta_generic_to_shared(p);
}
__device__ __forceinline__ void cp_async16(uint32_t dst, const void* src) {
    asm volatile("cp.async.cg.shared.global [%0], [%1], 16;\n"
                 :: "r"(dst), "l"(src));
}
#define CP_COMMIT() asm volatile("cp.async.commit_group;\n" ::: "memory")
#define CP_WAIT(n)  asm volatile("cp.async.wait_group %0;\n" :: "n"(n) : "memory")

__device__ __forceinline__ void ldsm4(uint32_t* r, uint32_t addr) {
    asm volatile("ldmatrix.sync.aligned.m8n8.x4.shared.b16 {%0,%1,%2,%3}, [%4];"
                 : "=r"(r[0]), "=r"(r[1]), "=r"(r[2]), "=r"(r[3]) : "r"(addr));
}
__device__ __forceinline__ void ldsm4t(uint32_t* r, uint32_t addr) {
    asm volatile("ldmatrix.sync.aligned.m8n8.x4.trans.shared.b16 {%0,%1,%2,%3}, [%4];"
                 : "=r"(r[0]), "=r"(r[1]), "=r"(r[2]), "=r"(r[3]) : "r"(addr));
}
__device__ __forceinline__ void mma16816(float* d, const uint32_t* a,
                                         const uint32_t* b) {
    asm volatile("mma.sync.aligned.m16n8k16.row.col.f32.bf16.bf16.f32 "
                 "{%0,%1,%2,%3}, {%4,%5,%6,%7}, {%8,%9}, {%0,%1,%2,%3};"
                 : "+f"(d[0]), "+f"(d[1]), "+f"(d[2]), "+f"(d[3])
                 : "r"(a[0]), "r"(a[1]), "r"(a[2]), "r"(a[3]),
                   "r"(b[0]), "r"(b[1]));
}
__device__ __forceinline__ float ex2f(float x) {
    float y;
    asm("ex2.approx.f32 %0, %1;" : "=f"(y) : "f"(x));
    return y;
}
__device__ __forceinline__ void pack_hilo(float x, float y,
                                          uint32_t& hw, uint32_t& lw) {
    __nv_bfloat162 h = __float22bfloat162_rn(make_float2(x, y));
    float2 hf = __bfloat1622float2(h);
    __nv_bfloat162 l = __float22bfloat162_rn(make_float2(x - hf.x, y - hf.y));
    hw = *(uint32_t*)&h;
    lw = *(uint32_t*)&l;
}

/* ==================== fp32 -> bf16 hi/lo split ============================ */
__global__ void cvt_split(const float* __restrict__ x,
                          __nv_bfloat16* __restrict__ hi,
                          __nv_bfloat16* __restrict__ lo, int n4)
{
    int i = blockIdx.x * blockDim.x + threadIdx.x;
    if (i >= n4) return;
    float4 v = ((const float4*)x)[i];
    __nv_bfloat16 h0 = __float2bfloat16(v.x);
    __nv_bfloat16 h1 = __float2bfloat16(v.y);
    __nv_bfloat16 h2 = __float2bfloat16(v.z);
    __nv_bfloat16 h3 = __float2bfloat16(v.w);
    __nv_bfloat16 l0 = __float2bfloat16(v.x - __bfloat162float(h0));
    __nv_bfloat16 l1 = __float2bfloat16(v.y - __bfloat162float(h1));
    __nv_bfloat16 l2 = __float2bfloat16(v.z - __bfloat162float(h2));
    __nv_bfloat16 l3 = __float2bfloat16(v.w - __bfloat162float(h3));
    __nv_bfloat162 hv0 = {h0, h1}, hv1 = {h2, h3};
    __nv_bfloat162 lv0 = {l0, l1}, lv1 = {l2, l3};
    uint2 hw, lw;
    hw.x = *(uint32_t*)&hv0; hw.y = *(uint32_t*)&hv1;
    lw.x = *(uint32_t*)&lv0; lw.y = *(uint32_t*)&lv1;
    ((uint2*)hi)[i] = hw;
    ((uint2*)lo)[i] = lw;
}

/* ============== HMMA GEMM: C = A*B^T + bias, 3xBF16 split ================= */
/* CTA 128x256, 16 warps (2x8 grid of 64x32 warp tiles), BK=32, 3-stage ring.*/
#define SA_HI 0
#define SA_LO (128 * 40)
#define SB_HI (2 * 128 * 40)
#define SB_LO (2 * 128 * 40 + 256 * 40)
#define GSTAGE_E (2 * 128 * 40 + 2 * 256 * 40)     /* 30720 elems */
#define GSTAGE_B (GSTAGE_E * 2)                    /* 61440 B     */
#define GSTAGES 3
#define GSMEM (GSTAGES * GSTAGE_B)                 /* 184320 B    */

__global__ void __launch_bounds__(512, 1) gemm_mma_bf16x3(
    const __nv_bfloat16* __restrict__ Ah, const __nv_bfloat16* __restrict__ Al,
    const __nv_bfloat16* __restrict__ Bh, const __nv_bfloat16* __restrict__ Bl,
    const float* __restrict__ bias, float* __restrict__ C, int N, int K)
{
    extern __shared__ __nv_bfloat16 smem[];
    const uint32_t sb = smem_u32(smem);

    const int tid  = threadIdx.x;
    const int lane = tid & 31;
    const int wid  = tid >> 5;
    const int wy   = wid >> 3;          /* 0..1 : 64-row band   */
    const int wx   = wid & 7;           /* 0..7 : 32-col band   */
    const int m0   = blockIdx.y * 128;
    const int n0   = blockIdx.x * 256;
    const int KT   = K / 32;

    /* loader: thread -> (row 0..127, 16B chunk) */
    const int lr = tid >> 2;            /* 0..127 */
    const int lc = (tid & 3) * 8;       /* 0,8,16,24 */
    const uint32_t doff = (uint32_t)(lr * 40 + lc) * 2;

    float acc[4][4][4];
#pragma unroll
    for (int mt = 0; mt < 4; mt++)
#pragma unroll
        for (int nt = 0; nt < 4; nt++)
#pragma unroll
            for (int j = 0; j < 4; j++) acc[mt][nt][j] = 0.f;

    const int a_row = wy * 64 + (lane & 15);
    const int a_col = (lane >> 4) * 8;
    const uint32_t a_off = (uint32_t)(a_row * 40 + a_col) * 2;
    const int b_row = wx * 32 + ((lane >> 4) << 3) + (lane & 7);
    const int b_col = ((lane >> 3) & 1) * 8;
    const uint32_t b_off = (uint32_t)(b_row * 40 + b_col) * 2;

#define LOAD_STAGE(kt, st) do {                                           \
        const int k0_ = (kt) * 32;                                        \
        const uint32_t s0_ = sb + (st) * GSTAGE_B + doff;                 \
        size_t asrc_ = (size_t)(m0 + lr) * K + k0_ + lc;                  \
        cp_async16(s0_ + SA_HI * 2, Ah + asrc_);                          \
        cp_async16(s0_ + SA_LO * 2, Al + asrc_);                          \
        _Pragma("unroll")                                                 \
        for (int p_ = 0; p_ < 2; p_++) {                                  \
            size_t bsrc_ = (size_t)(n0 + p_ * 128 + lr) * K + k0_ + lc;   \
            uint32_t d_ = s0_ + (uint32_t)(p_ * 128 * 40) * 2;            \
            cp_async16(d_ + SB_HI * 2, Bh + bsrc_);                       \
            cp_async16(d_ + SB_LO * 2, Bl + bsrc_);                       \
        }                                                                 \
    } while (0)

    LOAD_STAGE(0, 0);
    CP_COMMIT();
    LOAD_STAGE(1, 1);
    CP_COMMIT();

    int st = 0;
    for (int kt = 0; kt < KT; kt++) {
        CP_WAIT(1);
        __syncthreads();
        if (kt + 2 < KT) {
            int st2 = st + 2; if (st2 >= GSTAGES) st2 -= GSTAGES;
            LOAD_STAGE(kt + 2, st2);
            CP_COMMIT();
        }

        const uint32_t stb = sb + st * GSTAGE_B;
#pragma unroll
        for (int ks = 0; ks < 32; ks += 16) {
            const uint32_t kso = (uint32_t)ks * 2;
            uint32_t bh[4][2], bl[4][2];
#pragma unroll
            for (int nt2 = 0; nt2 < 2; nt2++) {
                uint32_t bo = stb + b_off + (uint32_t)(nt2 * 16 * 40) * 2 + kso;
                uint32_t r[4];
                ldsm4(r, bo + SB_HI * 2);
                bh[nt2 * 2][0] = r[0]; bh[nt2 * 2][1] = r[1];
                bh[nt2 * 2 + 1][0] = r[2]; bh[nt2 * 2 + 1][1] = r[3];
                ldsm4(r, bo + SB_LO * 2);
                bl[nt2 * 2][0] = r[0]; bl[nt2 * 2][1] = r[1];
                bl[nt2 * 2 + 1][0] = r[2]; bl[nt2 * 2 + 1][1] = r[3];
            }
#pragma unroll
            for (int mt = 0; mt < 4; mt++) {
                uint32_t ah[4], al[4];
                uint32_t ao = stb + a_off + (uint32_t)(mt * 16 * 40) * 2 + kso;
                ldsm4(ah, ao + SA_HI * 2);
                ldsm4(al, ao + SA_LO * 2);
#pragma unroll
                for (int nt = 0; nt < 4; nt++)
                    mma16816(acc[mt][nt], ah, bh[nt]);
#pragma unroll
                for (int nt = 0; nt < 4; nt++)
                    mma16816(acc[mt][nt], ah, bl[nt]);
#pragma unroll
                for (int nt = 0; nt < 4; nt++)
                    mma16816(acc[mt][nt], al, bh[nt]);
            }
        }
        st++; if (st >= GSTAGES) st -= GSTAGES;
    }
#undef LOAD_STAGE

#pragma unroll
    for (int mt = 0; mt < 4; mt++) {
        int row0 = m0 + wy * 64 + mt * 16 + (lane >> 2);
#pragma unroll
        for (int nt = 0; nt < 4; nt++) {
            int col = n0 + wx * 32 + nt * 8 + (lane & 3) * 2;
            float b0 = bias[col], b1 = bias[col + 1];
            float2 v0 = {acc[mt][nt][0] + b0, acc[mt][nt][1] + b1};
            float2 v1 = {acc[mt][nt][2] + b0, acc[mt][nt][3] + b1};
            *(float2*)(C + (size_t)row0 * N + col)       = v0;
            *(float2*)(C + (size_t)(row0 + 8) * N + col) = v1;
        }
    }
}

/* -------- RoPE + split qkv into bf16 hi/lo attention layouts -------------- */
__global__ void rope_split_kernel(const float* __restrict__ cosp,
                                  const float* __restrict__ sinp)
{
    int idx = blockIdx.x * blockDim.x + threadIdx.x;
    if (idx >= BS_ * QKV_OUT_) return;
    int col = idx % QKV_OUT_;
    int bs  = idx / QKV_OUT_;
    int b   = bs / S_;
    int s   = bs - b * S_;
    int d   = col & (D_ - 1);
    float v = g_qkv[idx];
    const float SCALE = 0.08838834764831845f;  /* 1/sqrt(128) */

    float val;
    size_t dst;
    __nv_bfloat16 *ph, *pl;
    if (col < NH_ * D_) {
        int h = col >> 7;
        float c  = cosp[s * D_ + d];
        float sn = sinp[s * D_ + d];
        float partner = g_qkv[(size_t)bs * QKV_OUT_ + (col ^ 64)];
        float r = (d < 64) ? -partner : partner;
        val = (v * c + r * sn) * SCALE;
        dst = (((size_t)b * NH_ + h) * S_ + s) * D_ + d;
        ph = g_qh; pl = g_ql;
    } else if (col < (NH_ + NKV_) * D_) {
        int kvh = (col - NH_ * D_) >> 7;
        float c  = cosp[s * D_ + d];
        float sn = sinp[s * D_ + d];
        float partner = g_qkv[(size_t)bs * QKV_OUT_ + (col ^ 64)];
        float r = (d < 64) ? -partner : partner;
        val = v * c + r * sn;
        dst = (((size_t)b * NKV_ + kvh) * S_ + s) * D_ + d;
        ph = g_kh; pl = g_kl;
    } else {
        int kvh = (col - (NH_ + NKV_) * D_) >> 7;
        val = v;
        dst = (((size_t)b * NKV_ + kvh) * S_ + s) * D_ + d;
        ph = g_vh; pl = g_vl;
    }
    __nv_bfloat16 hv = __float2bfloat16(val);
    ph[dst] = hv;
    pl[dst] = __float2bfloat16(val - __bfloat162float(hv));
}

/* ============ HMMA flash attention (sliding window, GQA) ================== */
#define AT_PAD 136
#define AQ_L   (128 * AT_PAD)
#define AST0   (2 * 128 * AT_PAD)
#define AMAT   (64 * AT_PAD)
#define ASTAGE (4 * AMAT)
#define ATTN_SMEM_B ((AST0 + 2 * ASTAGE) * 2)
#define LOG2E 1.4426950408889634f

__global__ void __launch_bounds__(256, 1) attn_mma()
{
    const int qbx = blockIdx.x, h = blockIdx.y, b = blockIdx.z;
    const int kvh = h >> 2;
    const int qlo = qbx * 128;

    extern __shared__ __nv_bfloat16 asmem[];
    const uint32_t sb = smem_u32(asmem);
    const int tid = threadIdx.x, lane = tid & 31, w = tid >> 5;

    const __nv_bfloat16* Qhg = g_qh + (((size_t)b * NH_ + h) * S_ + qlo) * D_;
    const __nv_bfloat16* Qlg = g_ql + (((size_t)b * NH_ + h) * S_ + qlo) * D_;
    const __nv_bfloat16* Khg = g_kh + ((size_t)b * NKV_ + kvh) * S_ * D_;
    const __nv_bfloat16* Klg = g_kl + ((size_t)b * NKV_ + kvh) * S_ * D_;
    const __nv_bfloat16* Vhg = g_vh + ((size_t)b * NKV_ + kvh) * S_ * D_;
    const __nv_bfloat16* Vlg = g_vl + ((size_t)b * NKV_ + kvh) * S_ * D_;

    for (int c = tid; c < 2048; c += 256) {
        int row = c >> 4, ch = c & 15;
        uint32_t dq = sb + (uint32_t)(row * AT_PAD + ch * 8) * 2;
        size_t src = (size_t)row * D_ + ch * 8;
        cp_async16(dq, Qhg + src);
        cp_async16(dq + AQ_L * 2, Qlg + src);
    }

#define LOAD_KV(kb, st) do {                                            \
        const int kbase_ = (kb) * 64;                                   \
        const uint32_t s0_ = sb + (uint32_t)(AST0 + (st) * ASTAGE) * 2; \
        for (int c = tid; c < 1024; c += 256) {                         \
            int row_ = c >> 4, ch_ = c & 15;                            \
            uint32_t d_ = s0_ + (uint32_t)(row_ * AT_PAD + ch_ * 8) * 2;\
            size_t src_ = (size_t)(kbase_ + row_) * D_ + ch_ * 8;       \
            cp_async16(d_,                Khg + src_);                  \
            cp_async16(d_ + AMAT * 2,     Klg + src_);                  \
            cp_async16(d_ + 2 * AMAT * 2, Vhg + src_);                  \
            cp_async16(d_ + 3 * AMAT * 2, Vlg + src_);                  \
        } } while (0)

    int kstart = qlo - (WINDOW_ - 1);
    if (kstart < 0) kstart = 0;
    const int kb0 = kstart >> 6;
    const int kb1 = (qlo + 127) >> 6;

    LOAD_KV(kb0, 0);
    CP_COMMIT();

    float oacc[16][4];
#pragma unroll
    for (int nf = 0; nf < 16; nf++)
#pragma unroll
        for (int j = 0; j < 4; j++) oacc[nf][j] = 0.f;
    float m0 = -1e30f, m1 = -1e30f, l0 = 0.f, l1 = 0.f;

    const int qg0 = qlo + w * 16 + (lane >> 2);
    const int qg1 = qg0 + 8;
    const uint32_t qrow_off =
        (uint32_t)((w * 16 + (lane & 15)) * AT_PAD + (lane >> 4) * 8) * 2;
    const uint32_t krow_off =
        (uint32_t)((((lane >> 4) << 3) + (lane & 7)) * AT_PAD +
                   ((lane >> 3) & 1) * 8) * 2;
    const uint32_t vrow_off =
        (uint32_t)((lane & 15) * AT_PAD + (lane >> 4) * 8) * 2;

    for (int kb = kb0; kb <= kb1; kb++) {
        const int st = (kb - kb0) & 1;
        if (kb < kb1) {
            LOAD_KV(kb + 1, st ^ 1);
            CP_COMMIT();
            CP_WAIT(1);
        } else {
            CP_WAIT(0);
        }
        __syncthreads();

        const uint32_t stb = sb + (uint32_t)(AST0 + st * ASTAGE) * 2;
        const int kbase = kb * 64;

        float sacc[8][4];
#pragma unroll
        for (int j = 0; j < 8; j++)
#pragma unroll
            for (int i = 0; i < 4; i++) sacc[j][i] = 0.f;

#pragma unroll
        for (int kk = 0; kk < 8; kk++) {
            uint32_t qh[4], ql[4];
            const uint32_t qoff = sb + qrow_off + kk * 32;
            ldsm4(qh, qoff);
            ldsm4(ql, qoff + AQ_L * 2);
#pragma unroll
            for (int nb = 0; nb < 4; nb++) {
                uint32_t kh[4], kl[4];
                const uint32_t koff = stb + krow_off +
                    (uint32_t)(nb * 16 * AT_PAD) * 2 + kk * 32;
                ldsm4(kh, koff);
                ldsm4(kl, koff + AMAT * 2);
                mma16816(sacc[2 * nb],     qh, kh);
                mma16816(sacc[2 * nb],     qh, kl);
                mma16816(sacc[2 * nb],     ql, kh);
                mma16816(sacc[2 * nb + 1], qh, &kh[2]);
                mma16816(sacc[2 * nb + 1], qh, &kl[2]);
                mma16816(sacc[2 * nb + 1], ql, &kh[2]);
            }
        }

#pragma unroll
        for (int j = 0; j < 8; j++) {
            const int kg0 = kbase + 8 * j + 2 * (lane & 3);
            const int kg1 = kg0 + 1;
            if (!(kg0 <= qg0 && qg0 - kg0 < WINDOW_)) sacc[j][0] = -1e30f;
            if (!(kg1 <= qg0 && qg0 - kg1 < WINDOW_)) sacc[j][1] = -1e30f;
            if (!(kg0 <= qg1 && qg1 - kg0 < WINDOW_)) sacc[j][2] = -1e30f;
            if (!(kg1 <= qg1 && qg1 - kg1 < WINDOW_)) sacc[j][3] = -1e30f;
        }

        float mx0 = m0, mx1 = m1;
#pragma unroll
        for (int j = 0; j < 8; j++) {
            mx0 = fmaxf(mx0, fmaxf(sacc[j][0], sacc[j][1]));
            mx1 = fmaxf(mx1, fmaxf(sacc[j][2], sacc[j][3]));
        }
        mx0 = fmaxf(mx0, __shfl_xor_sync(0xffffffffu, mx0, 1));
        mx0 = fmaxf(mx0, __shfl_xor_sync(0xffffffffu, mx0, 2));
        mx1 = fmaxf(mx1, __shfl_xor_sync(0xffffffffu, mx1, 1));
        mx1 = fmaxf(mx1, __shfl_xor_sync(0xffffffffu, mx1, 2));

        const float sc0 = ex2f((m0 - mx0) * LOG2E);
        const float sc1 = ex2f((m1 - mx1) * LOG2E);
        float la0 = 0.f, la1 = 0.f;
#pragma unroll
        for (int j = 0; j < 8; j++) {
            float p0 = (sacc[j][0] > -1e29f) ? ex2f((sacc[j][0] - mx0) * LOG2E) : 0.f;
            float p1 = (sacc[j][1] > -1e29f) ? ex2f((sacc[j][1] - mx0) * LOG2E) : 0.f;
            float p2 = (sacc[j][2] > -1e29f) ? ex2f((sacc[j][2] - mx1) * LOG2E) : 0.f;
            float p3 = (sacc[j][3] > -1e29f) ? ex2f((sacc[j][3] - mx1) * LOG2E) : 0.f;
            sacc[j][0] = p0; sacc[j][1] = p1; sacc[j][2] = p2; sacc[j][3] = p3;
            la0 += p0 + p1;
            la1 += p2 + p3;
        }
        la0 += __shfl_xor_sync(0xffffffffu, la0, 1);
        la0 += __shfl_xor_sync(0xffffffffu, la0, 2);
        la1 += __shfl_xor_sync(0xffffffffu, la1, 1);
        la1 += __shfl_xor_sync(0xffffffffu, la1, 2);
        l0 = l0 * sc0 + la0;
        l1 = l1 * sc1 + la1;
        m0 = mx0; m1 = mx1;

#pragma unroll
        for (int nf = 0; nf < 16; nf++) {
            oacc[nf][0] *= sc0; oacc[nf][1] *= sc0;
            oacc[nf][2] *= sc1; oacc[nf][3] *= sc1;
        }

#pragma unroll
        for (int s4 = 0; s4 < 4; s4++) {
            uint32_t ah[4], al[4];
            pack_hilo(sacc[2 * s4][0],     sacc[2 * s4][1],     ah[0], al[0]);
            pack_hilo(sacc[2 * s4][2],     sacc[2 * s4][3],     ah[1], al[1]);
            pack_hilo(sacc[2 * s4 + 1][0], sacc[2 * s4 + 1][1], ah[2], al[2]);
            pack_hilo(sacc[2 * s4 + 1][2], sacc[2 * s4 + 1][3], ah[3], al[3]);

            const uint32_t vbase = stb + 2 * AMAT * 2 + vrow_off +
                                   (uint32_t)(s4 * 16 * AT_PAD) * 2;
#pragma unroll
            for (int db = 0; db < 8; db++) {
                uint32_t vh[4], vl[4];
                const uint32_t voff = vbase + db * 32;
                ldsm4t(vh, voff);
                ldsm4t(vl, voff + AMAT * 2);
                mma16816(oacc[2 * db],     ah, vh);
                mma16816(oacc[2 * db],     ah, vl);
                mma16816(oacc[2 * db],     al, vh);
                mma16816(oacc[2 * db + 1], ah, &vh[2]);
                mma16816(oacc[2 * db + 1], ah, &vl[2]);
                mma16816(oacc[2 * db + 1], al, &vh[2]);
            }
        }
        __syncthreads();
    }
#undef LOAD_KV

    const float inv0 = 1.f / l0;
    const float inv1 = 1.f / l1;
    const size_t o0 = (size_t)(b * S_ + qg0) * (NH_ * D_) + h * D_;
    const size_t o1 = (size_t)(b * S_ + qg1) * (NH_ * D_) + h * D_;
#pragma unroll
    for (int nf = 0; nf < 16; nf++) {
        const int dc = 8 * nf + 2 * (lane & 3);
        uint32_t hw, lw;
        pack_hilo(oacc[nf][0] * inv0, oacc[nf][1] * inv0, hw, lw);
        *(uint32_t*)(g_at_hi + o0 + dc) = hw;
        *(uint32_t*)(g_at_lo + o0 + dc) = lw;
        pack_hilo(oacc[nf][2] * inv1, oacc[nf][3] * inv1, hw, lw);
        *(uint32_t*)(g_at_hi + o1 + dc) = hw;
        *(uint32_t*)(g_at_lo + o1 + dc) = lw;
    }
}

/* --------------------------------- launch --------------------------------- */
extern "C" void kernel_launch(void* const* d_in, const int* in_sizes, int n_in,
                              void* d_out, int out_size)
{
    const float* hidden = (const float*)d_in[0];
    const float* cosp   = (const float*)d_in[1];
    const float* sinp   = (const float*)d_in[2];
    const float* w_qkv  = (const float*)d_in[3];
    const float* b_qkv  = (const float*)d_in[4];
    const float* w_o    = (const float*)d_in[5];
    const float* b_o    = (const float*)d_in[6];
    float* out = (float*)d_out;

    float *p_qkv;
    __nv_bfloat16 *p_h_hi, *p_h_lo, *p_wq_hi, *p_wq_lo, *p_wo_hi, *p_wo_lo,
                  *p_at_hi, *p_at_lo;
    cudaGetSymbolAddress((void**)&p_qkv, g_qkv);
    cudaGetSymbolAddress((void**)&p_h_hi, g_h_hi);
    cudaGetSymbolAddress((void**)&p_h_lo, g_h_lo);
    cudaGetSymbolAddress((void**)&p_wq_hi, g_wq_hi);
    cudaGetSymbolAddress((void**)&p_wq_lo, g_wq_lo);
    cudaGetSymbolAddress((void**)&p_wo_hi, g_wo_hi);
    cudaGetSymbolAddress((void**)&p_wo_lo, g_wo_lo);
    cudaGetSymbolAddress((void**)&p_at_hi, g_at_hi);
    cudaGetSymbolAddress((void**)&p_at_lo, g_at_lo);

    cudaFuncSetAttribute(gemm_mma_bf16x3,
                         cudaFuncAttributeMaxDynamicSharedMemorySize, GSMEM);
    cudaFuncSetAttribute(attn_mma,
                         cudaFuncAttributeMaxDynamicSharedMemorySize, ATTN_SMEM_B);

    /* converts */
    cvt_split<<<(BS_ * HID_ / 4 + 255) / 256, 256>>>(hidden, p_h_hi, p_h_lo,
                                                     BS_ * HID_ / 4);
    cvt_split<<<(QKV_OUT_ * HID_ / 4 + 255) / 256, 256>>>(w_qkv, p_wq_hi, p_wq_lo,
                                                          QKV_OUT_ * HID_ / 4);
    cvt_split<<<(HID_ * HID_ / 4 + 255) / 256, 256>>>(w_o, p_wo_hi, p_wo_lo,
                                                      HID_ * HID_ / 4);

    /* 1) qkv = hidden @ w_qkv^T + b_qkv */
    gemm_mma_bf16x3<<<dim3(QKV_OUT_ / 256, BS_ / 128), 512, GSMEM>>>(
        p_h_hi, p_h_lo, p_wq_hi, p_wq_lo, b_qkv, p_qkv, QKV_OUT_, HID_);

    /* 2) RoPE + split to bf16 hi/lo */
    rope_split_kernel<<<(BS_ * QKV_OUT_ + 255) / 256, 256>>>(cosp, sinp);

    /* 3) HMMA flash attention (writes bf16 hi/lo directly) */
    attn_mma<<<dim3(S_ / 128, NH_, B_), 256, ATTN_SMEM_B>>>();

    /* 4) out = attn @ w_o^T + b_o */
    gemm_mma_bf16x3<<<dim3(HID_ / 256, BS_ / 128), 512, GSMEM>>>(
        p_at_hi, p_at_lo, p_wo_hi, p_wo_lo, b_o, out, HID_, HID_);
}

// round 8
// speedup vs baseline: 2.9795x; 1.0033x over previous
#include <cuda_runtime.h>
#include <cuda_bf16.h>
#include <cstdint>
#include <math.h>

#define B_ 2
#define S_ 1024
#define HID_ 4096
#define NH_ 32
#define NKV_ 8
#define D_ 128
#define WINDOW_ 512
#define QKV_OUT_ ((NH_ + 2 * NKV_) * D_)   /* 6144 */
#define BS_ (B_ * S_)                      /* 2048 */

/* ------------------------- scratch (static device globals) ---------------- */
__device__ __nv_bfloat16 g_qh[B_ * NH_ * S_ * D_];
__device__ __nv_bfloat16 g_ql[B_ * NH_ * S_ * D_];
__device__ __nv_bfloat16 g_kh[B_ * NKV_ * S_ * D_];
__device__ __nv_bfloat16 g_kl[B_ * NKV_ * S_ * D_];
__device__ __nv_bfloat16 g_vh[B_ * NKV_ * S_ * D_];
__device__ __nv_bfloat16 g_vl[B_ * NKV_ * S_ * D_];

__device__ __nv_bfloat16 g_h_hi[BS_ * HID_];
__device__ __nv_bfloat16 g_h_lo[BS_ * HID_];
__device__ __nv_bfloat16 g_wq_hi[QKV_OUT_ * HID_];
__device__ __nv_bfloat16 g_wq_lo[QKV_OUT_ * HID_];
__device__ __nv_bfloat16 g_wo_hi[HID_ * HID_];
__device__ __nv_bfloat16 g_wo_lo[HID_ * HID_];
__device__ __nv_bfloat16 g_at_hi[BS_ * HID_];
__device__ __nv_bfloat16 g_at_lo[BS_ * HID_];

/* ============================ PTX helpers (base ISA only) ================= */
__device__ __forceinline__ uint32_t smem_u32(const void* p) {
    return (uint32_t)__cvta_generic_to_shared(p);
}
__device__ __forceinline__ void cp_async16(uint32_t dst, const void* src) {
    asm volatile("cp.async.cg.shared.global [%0], [%1], 16;\n"
                 :: "r"(dst), "l"(src));
}
#define CP_COMMIT() asm volatile("cp.async.commit_group;\n" ::: "memory")
#define CP_WAIT(n)  asm volatile("cp.async.wait_group %0;\n" :: "n"(n) : "memory")

__device__ __forceinline__ void ldsm4(uint32_t* r, uint32_t addr) {
    asm volatile("ldmatrix.sync.aligned.m8n8.x4.shared.b16 {%0,%1,%2,%3}, [%4];"
                 : "=r"(r[0]), "=r"(r[1]), "=r"(r[2]), "=r"(r[3]) : "r"(addr));
}
__device__ __forceinline__ void ldsm4t(uint32_t* r, uint32_t addr) {
    asm volatile("ldmatrix.sync.aligned.m8n8.x4.trans.shared.b16 {%0,%1,%2,%3}, [%4];"
                 : "=r"(r[0]), "=r"(r[1]), "=r"(r[2]), "=r"(r[3]) : "r"(addr));
}
__device__ __forceinline__ void mma16816(float* d, const uint32_t* a,
                                         const uint32_t* b) {
    asm volatile("mma.sync.aligned.m16n8k16.row.col.f32.bf16.bf16.f32 "
                 "{%0,%1,%2,%3}, {%4,%5,%6,%7}, {%8,%9}, {%0,%1,%2,%3};"
                 : "+f"(d[0]), "+f"(d[1]), "+f"(d[2]), "+f"(d[3])
                 : "r"(a[0]), "r"(a[1]), "r"(a[2]), "r"(a[3]),
                   "r"(b[0]), "r"(b[1]));
}
__device__ __forceinline__ float ex2f(float x) {
    float y;
    asm("ex2.approx.f32 %0, %1;" : "=f"(y) : "f"(x));
    return y;
}
__device__ __forceinline__ void pack_hilo(float x, float y,
                                          uint32_t& hw, uint32_t& lw) {
    __nv_bfloat162 h = __float22bfloat162_rn(make_float2(x, y));
    float2 hf = __bfloat1622float2(h);
    __nv_bfloat162 l = __float22bfloat162_rn(make_float2(x - hf.x, y - hf.y));
    hw = *(uint32_t*)&h;
    lw = *(uint32_t*)&l;
}

/* ==================== fp32 -> bf16 hi/lo split ============================ */
__global__ void cvt_split(const float* __restrict__ x,
                          __nv_bfloat16* __restrict__ hi,
                          __nv_bfloat16* __restrict__ lo, int n4)
{
    int i = blockIdx.x * blockDim.x + threadIdx.x;
    if (i >= n4) return;
    float4 v = ((const float4*)x)[i];
    __nv_bfloat16 h0 = __float2bfloat16(v.x);
    __nv_bfloat16 h1 = __float2bfloat16(v.y);
    __nv_bfloat16 h2 = __float2bfloat16(v.z);
    __nv_bfloat16 h3 = __float2bfloat16(v.w);
    __nv_bfloat16 l0 = __float2bfloat16(v.x - __bfloat162float(h0));
    __nv_bfloat16 l1 = __float2bfloat16(v.y - __bfloat162float(h1));
    __nv_bfloat16 l2 = __float2bfloat16(v.z - __bfloat162float(h2));
    __nv_bfloat16 l3 = __float2bfloat16(v.w - __bfloat162float(h3));
    __nv_bfloat162 hv0 = {h0, h1}, hv1 = {h2, h3};
    __nv_bfloat162 lv0 = {l0, l1}, lv1 = {l2, l3};
    uint2 hw, lw;
    hw.x = *(uint32_t*)&hv0; hw.y = *(uint32_t*)&hv1;
    lw.x = *(uint32_t*)&lv0; lw.y = *(uint32_t*)&lv1;
    ((uint2*)hi)[i] = hw;
    ((uint2*)lo)[i] = lw;
}

/* ============== HMMA GEMM: C = A*B^T + bias, 3xBF16 split ================= */
/* CTA 128x256, 16 warps (2x8 grid of 64x32 warp tiles), BK=32, 3-stage ring.
   mode 0: plain fp32 store to C.  mode 1: fused RoPE/split epilogue (QKV). */
#define SA_HI 0
#define SA_LO (128 * 40)
#define SB_HI (2 * 128 * 40)
#define SB_LO (2 * 128 * 40 + 256 * 40)
#define GSTAGE_E (2 * 128 * 40 + 2 * 256 * 40)     /* 30720 elems */
#define GSTAGE_B (GSTAGE_E * 2)                    /* 61440 B     */
#define GSTAGES 3
#define GSMEM (GSTAGES * GSTAGE_B)                 /* 184320 B    */
#define CPITCH 260

__global__ void __launch_bounds__(512, 1) gemm_mma_bf16x3(
    const __nv_bfloat16* __restrict__ Ah, const __nv_bfloat16* __restrict__ Al,
    const __nv_bfloat16* __restrict__ Bh, const __nv_bfloat16* __restrict__ Bl,
    const float* __restrict__ bias, float* __restrict__ C,
    const float* __restrict__ cosp, const float* __restrict__ sinp,
    int N, int K, int mode)
{
    extern __shared__ __nv_bfloat16 smem[];
    const uint32_t sb = smem_u32(smem);

    const int tid  = threadIdx.x;
    const int lane = tid & 31;
    const int wid  = tid >> 5;
    const int wy   = wid >> 3;          /* 0..1 : 64-row band   */
    const int wx   = wid & 7;           /* 0..7 : 32-col band   */
    const int m0   = blockIdx.y * 128;
    const int n0   = blockIdx.x * 256;
    const int KT   = K / 32;

    const int lr = tid >> 2;            /* 0..127 */
    const int lc = (tid & 3) * 8;       /* 0,8,16,24 */
    const uint32_t doff = (uint32_t)(lr * 40 + lc) * 2;

    float acc[4][4][4];
#pragma unroll
    for (int mt = 0; mt < 4; mt++)
#pragma unroll
        for (int nt = 0; nt < 4; nt++)
#pragma unroll
            for (int j = 0; j < 4; j++) acc[mt][nt][j] = 0.f;

    const int a_row = wy * 64 + (lane & 15);
    const int a_col = (lane >> 4) * 8;
    const uint32_t a_off = (uint32_t)(a_row * 40 + a_col) * 2;
    const int b_row = wx * 32 + ((lane >> 4) << 3) + (lane & 7);
    const int b_col = ((lane >> 3) & 1) * 8;
    const uint32_t b_off = (uint32_t)(b_row * 40 + b_col) * 2;

#define LOAD_STAGE(kt, st) do {                                           \
        const int k0_ = (kt) * 32;                                        \
        const uint32_t s0_ = sb + (st) * GSTAGE_B + doff;                 \
        size_t asrc_ = (size_t)(m0 + lr) * K + k0_ + lc;                  \
        cp_async16(s0_ + SA_HI * 2, Ah + asrc_);                          \
        cp_async16(s0_ + SA_LO * 2, Al + asrc_);                          \
        _Pragma("unroll")                                                 \
        for (int p_ = 0; p_ < 2; p_++) {                                  \
            size_t bsrc_ = (size_t)(n0 + p_ * 128 + lr) * K + k0_ + lc;   \
            uint32_t d_ = s0_ + (uint32_t)(p_ * 128 * 40) * 2;            \
            cp_async16(d_ + SB_HI * 2, Bh + bsrc_);                       \
            cp_async16(d_ + SB_LO * 2, Bl + bsrc_);                       \
        }                                                                 \
    } while (0)

    LOAD_STAGE(0, 0);
    CP_COMMIT();
    LOAD_STAGE(1, 1);
    CP_COMMIT();

    int st = 0;
    for (int kt = 0; kt < KT; kt++) {
        if (kt + 1 < KT) { CP_WAIT(1); } else { CP_WAIT(0); }
        __syncthreads();
        if (kt + 2 < KT) {
            int st2 = st + 2; if (st2 >= GSTAGES) st2 -= GSTAGES;
            LOAD_STAGE(kt + 2, st2);
            CP_COMMIT();
        }

        const uint32_t stb = sb + st * GSTAGE_B;
#pragma unroll
        for (int ks = 0; ks < 32; ks += 16) {
            const uint32_t kso = (uint32_t)ks * 2;
            uint32_t bh[4][2], bl[4][2];
#pragma unroll
            for (int nt2 = 0; nt2 < 2; nt2++) {
                uint32_t bo = stb + b_off + (uint32_t)(nt2 * 16 * 40) * 2 + kso;
                uint32_t r[4];
                ldsm4(r, bo + SB_HI * 2);
                bh[nt2 * 2][0] = r[0]; bh[nt2 * 2][1] = r[1];
                bh[nt2 * 2 + 1][0] = r[2]; bh[nt2 * 2 + 1][1] = r[3];
                ldsm4(r, bo + SB_LO * 2);
                bl[nt2 * 2][0] = r[0]; bl[nt2 * 2][1] = r[1];
                bl[nt2 * 2 + 1][0] = r[2]; bl[nt2 * 2 + 1][1] = r[3];
            }
#pragma unroll
            for (int mt = 0; mt < 4; mt++) {
                uint32_t ah[4], al[4];
                uint32_t ao = stb + a_off + (uint32_t)(mt * 16 * 40) * 2 + kso;
                ldsm4(ah, ao + SA_HI * 2);
                ldsm4(al, ao + SA_LO * 2);
#pragma unroll
                for (int nt = 0; nt < 4; nt++)
                    mma16816(acc[mt][nt], ah, bh[nt]);
#pragma unroll
                for (int nt = 0; nt < 4; nt++)
                    mma16816(acc[mt][nt], ah, bl[nt]);
#pragma unroll
                for (int nt = 0; nt < 4; nt++)
                    mma16816(acc[mt][nt], al, bh[nt]);
            }
        }
        st++; if (st >= GSTAGES) st -= GSTAGES;
    }
#undef LOAD_STAGE

    if (mode == 0) {
        /* plain epilogue: C = acc + bias (fp32) */
#pragma unroll
        for (int mt = 0; mt < 4; mt++) {
            int row0 = m0 + wy * 64 + mt * 16 + (lane >> 2);
#pragma unroll
            for (int nt = 0; nt < 4; nt++) {
                int col = n0 + wx * 32 + nt * 8 + (lane & 3) * 2;
                float b0 = bias[col], b1 = bias[col + 1];
                float2 v0 = {acc[mt][nt][0] + b0, acc[mt][nt][1] + b1};
                float2 v1 = {acc[mt][nt][2] + b0, acc[mt][nt][3] + b1};
                *(float2*)(C + (size_t)row0 * N + col)       = v0;
                *(float2*)(C + (size_t)(row0 + 8) * N + col) = v1;
            }
        }
    } else {
        /* fused RoPE + hi/lo split epilogue.
           CTA band = 256 cols = exactly 2 heads; rotate partner in-band. */
        __syncthreads();                    /* smem free for reuse */
        float* sC = (float*)smem;           /* [128][CPITCH] fp32  */
#pragma unroll
        for (int mt = 0; mt < 4; mt++) {
            int r0 = wy * 64 + mt * 16 + (lane >> 2);
#pragma unroll
            for (int nt = 0; nt < 4; nt++) {
                int cl = wx * 32 + nt * 8 + (lane & 3) * 2;
                float b0 = bias[n0 + cl], b1 = bias[n0 + cl + 1];
                *(float2*)&sC[r0 * CPITCH + cl] =
                    make_float2(acc[mt][nt][0] + b0, acc[mt][nt][1] + b1);
                *(float2*)&sC[(r0 + 8) * CPITCH + cl] =
                    make_float2(acc[mt][nt][2] + b0, acc[mt][nt][3] + b1);
            }
        }
        __syncthreads();

        const float SCALE = 0.08838834764831845f;   /* 1/sqrt(128) */
        for (int e = tid; e < 8192; e += 512) {
            int i  = e & 31;
            int hl = (e >> 5) & 1;
            int r  = e >> 6;
            int d0 = 2 * i;
            int row = m0 + r;
            int bb = row >> 10, s = row & 1023;

            float2 vlo = *(float2*)&sC[r * CPITCH + hl * 128 + d0];
            float2 vhi = *(float2*)&sC[r * CPITCH + hl * 128 + 64 + d0];
            int cg = n0 + hl * 128;

            float o0, o1, o2, o3;
            __nv_bfloat16 *ph, *pl;
            size_t base;
            if (cg < NH_ * D_) {
                float2 c_lo = *(const float2*)&cosp[s * D_ + d0];
                float2 c_hi = *(const float2*)&cosp[s * D_ + 64 + d0];
                float2 s_lo = *(const float2*)&sinp[s * D_ + d0];
                float2 s_hi = *(const float2*)&sinp[s * D_ + 64 + d0];
                int h = cg >> 7;
                o0 = (vlo.x * c_lo.x - vhi.x * s_lo.x) * SCALE;
                o1 = (vlo.y * c_lo.y - vhi.y * s_lo.y) * SCALE;
                o2 = (vhi.x * c_hi.x + vlo.x * s_hi.x) * SCALE;
                o3 = (vhi.y * c_hi.y + vlo.y * s_hi.y) * SCALE;
                base = (((size_t)bb * NH_ + h) * S_ + s) * D_;
                ph = g_qh; pl = g_ql;
            } else if (cg < (NH_ + NKV_) * D_) {
                float2 c_lo = *(const float2*)&cosp[s * D_ + d0];
                float2 c_hi = *(const float2*)&cosp[s * D_ + 64 + d0];
                float2 s_lo = *(const float2*)&sinp[s * D_ + d0];
                float2 s_hi = *(const float2*)&sinp[s * D_ + 64 + d0];
                int kvh = (cg - NH_ * D_) >> 7;
                o0 = vlo.x * c_lo.x - vhi.x * s_lo.x;
                o1 = vlo.y * c_lo.y - vhi.y * s_lo.y;
                o2 = vhi.x * c_hi.x + vlo.x * s_hi.x;
                o3 = vhi.y * c_hi.y + vlo.y * s_hi.y;
                base = (((size_t)bb * NKV_ + kvh) * S_ + s) * D_;
                ph = g_kh; pl = g_kl;
            } else {
                int kvh = (cg - (NH_ + NKV_) * D_) >> 7;
                o0 = vlo.x; o1 = vlo.y; o2 = vhi.x; o3 = vhi.y;
                base = (((size_t)bb * NKV_ + kvh) * S_ + s) * D_;
                ph = g_vh; pl = g_vl;
            }
            uint32_t hw, lw;
            pack_hilo(o0, o1, hw, lw);
            *(uint32_t*)(ph + base + d0) = hw;
            *(uint32_t*)(pl + base + d0) = lw;
            pack_hilo(o2, o3, hw, lw);
            *(uint32_t*)(ph + base + 64 + d0) = hw;
            *(uint32_t*)(pl + base + 64 + d0) = lw;
        }
    }
}

/* ============ HMMA flash attention (sliding window, GQA) ================== */
#define AT_PAD 136
#define AQ_L   (128 * AT_PAD)
#define AST0   (2 * 128 * AT_PAD)
#define AMAT   (64 * AT_PAD)
#define ASTAGE (4 * AMAT)
#define ATTN_SMEM_B ((AST0 + 2 * ASTAGE) * 2)
#define LOG2E 1.4426950408889634f

__global__ void __launch_bounds__(256, 1) attn_mma()
{
    const int qbx = blockIdx.x, h = blockIdx.y, b = blockIdx.z;
    const int kvh = h >> 2;
    const int qlo = qbx * 128;

    extern __shared__ __nv_bfloat16 asmem[];
    const uint32_t sb = smem_u32(asmem);
    const int tid = threadIdx.x, lane = tid & 31, w = tid >> 5;

    const __nv_bfloat16* Qhg = g_qh + (((size_t)b * NH_ + h) * S_ + qlo) * D_;
    const __nv_bfloat16* Qlg = g_ql + (((size_t)b * NH_ + h) * S_ + qlo) * D_;
    const __nv_bfloat16* Khg = g_kh + ((size_t)b * NKV_ + kvh) * S_ * D_;
    const __nv_bfloat16* Klg = g_kl + ((size_t)b * NKV_ + kvh) * S_ * D_;
    const __nv_bfloat16* Vhg = g_vh + ((size_t)b * NKV_ + kvh) * S_ * D_;
    const __nv_bfloat16* Vlg = g_vl + ((size_t)b * NKV_ + kvh) * S_ * D_;

    for (int c = tid; c < 2048; c += 256) {
        int row = c >> 4, ch = c & 15;
        uint32_t dq = sb + (uint32_t)(row * AT_PAD + ch * 8) * 2;
        size_t src = (size_t)row * D_ + ch * 8;
        cp_async16(dq, Qhg + src);
        cp_async16(dq + AQ_L * 2, Qlg + src);
    }

#define LOAD_KV(kb, st) do {                                            \
        const int kbase_ = (kb) * 64;                                   \
        const uint32_t s0_ = sb + (uint32_t)(AST0 + (st) * ASTAGE) * 2; \
        for (int c = tid; c < 1024; c += 256) {                         \
            int row_ = c >> 4, ch_ = c & 15;                            \
            uint32_t d_ = s0_ + (uint32_t)(row_ * AT_PAD + ch_ * 8) * 2;\
            size_t src_ = (size_t)(kbase_ + row_) * D_ + ch_ * 8;       \
            cp_async16(d_,                Khg + src_);                  \
            cp_async16(d_ + AMAT * 2,     Klg + src_);                  \
            cp_async16(d_ + 2 * AMAT * 2, Vhg + src_);                  \
            cp_async16(d_ + 3 * AMAT * 2, Vlg + src_);                  \
        } } while (0)

    int kstart = qlo - (WINDOW_ - 1);
    if (kstart < 0) kstart = 0;
    const int kb0 = kstart >> 6;
    const int kb1 = (qlo + 127) >> 6;

    LOAD_KV(kb0, 0);
    CP_COMMIT();

    float oacc[16][4];
#pragma unroll
    for (int nf = 0; nf < 16; nf++)
#pragma unroll
        for (int j = 0; j < 4; j++) oacc[nf][j] = 0.f;
    float m0 = -1e30f, m1 = -1e30f, l0 = 0.f, l1 = 0.f;

    const int qg0 = qlo + w * 16 + (lane >> 2);
    const int qg1 = qg0 + 8;
    const uint32_t qrow_off =
        (uint32_t)((w * 16 + (lane & 15)) * AT_PAD + (lane >> 4) * 8) * 2;
    const uint32_t krow_off =
        (uint32_t)((((lane >> 4) << 3) + (lane & 7)) * AT_PAD +
                   ((lane >> 3) & 1) * 8) * 2;
    const uint32_t vrow_off =
        (uint32_t)((lane & 15) * AT_PAD + (lane >> 4) * 8) * 2;

    for (int kb = kb0; kb <= kb1; kb++) {
        const int st = (kb - kb0) & 1;
        if (kb < kb1) {
            LOAD_KV(kb + 1, st ^ 1);
            CP_COMMIT();
            CP_WAIT(1);
        } else {
            CP_WAIT(0);
        }
        __syncthreads();

        const uint32_t stb = sb + (uint32_t)(AST0 + st * ASTAGE) * 2;
        const int kbase = kb * 64;

        float sacc[8][4];
#pragma unroll
        for (int j = 0; j < 8; j++)
#pragma unroll
            for (int i = 0; i < 4; i++) sacc[j][i] = 0.f;

#pragma unroll
        for (int kk = 0; kk < 8; kk++) {
            uint32_t qh[4], ql[4];
            const uint32_t qoff = sb + qrow_off + kk * 32;
            ldsm4(qh, qoff);
            ldsm4(ql, qoff + AQ_L * 2);
#pragma unroll
            for (int nb = 0; nb < 4; nb++) {
                uint32_t kh[4], kl[4];
                const uint32_t koff = stb + krow_off +
                    (uint32_t)(nb * 16 * AT_PAD) * 2 + kk * 32;
                ldsm4(kh, koff);
                ldsm4(kl, koff + AMAT * 2);
                mma16816(sacc[2 * nb],     qh, kh);
                mma16816(sacc[2 * nb],     qh, kl);
                mma16816(sacc[2 * nb],     ql, kh);
                mma16816(sacc[2 * nb + 1], qh, &kh[2]);
                mma16816(sacc[2 * nb + 1], qh, &kl[2]);
                mma16816(sacc[2 * nb + 1], ql, &kh[2]);
            }
        }

#pragma unroll
        for (int j = 0; j < 8; j++) {
            const int kg0 = kbase + 8 * j + 2 * (lane & 3);
            const int kg1 = kg0 + 1;
            if (!(kg0 <= qg0 && qg0 - kg0 < WINDOW_)) sacc[j][0] = -1e30f;
            if (!(kg1 <= qg0 && qg0 - kg1 < WINDOW_)) sacc[j][1] = -1e30f;
            if (!(kg0 <= qg1 && qg1 - kg0 < WINDOW_)) sacc[j][2] = -1e30f;
            if (!(kg1 <= qg1 && qg1 - kg1 < WINDOW_)) sacc[j][3] = -1e30f;
        }

        float mx0 = m0, mx1 = m1;
#pragma unroll
        for (int j = 0; j < 8; j++) {
            mx0 = fmaxf(mx0, fmaxf(sacc[j][0], sacc[j][1]));
            mx1 = fmaxf(mx1, fmaxf(sacc[j][2], sacc[j][3]));
        }
        mx0 = fmaxf(mx0, __shfl_xor_sync(0xffffffffu, mx0, 1));
        mx0 = fmaxf(mx0, __shfl_xor_sync(0xffffffffu, mx0, 2));
        mx1 = fmaxf(mx1, __shfl_xor_sync(0xffffffffu, mx1, 1));
        mx1 = fmaxf(mx1, __shfl_xor_sync(0xffffffffu, mx1, 2));

        const float sc0 = ex2f((m0 - mx0) * LOG2E);
        const float sc1 = ex2f((m1 - mx1) * LOG2E);
        float la0 = 0.f, la1 = 0.f;
#pragma unroll
        for (int j = 0; j < 8; j++) {
            float p0 = (sacc[j][0] > -1e29f) ? ex2f((sacc[j][0] - mx0) * LOG2E) : 0.f;
            float p1 = (sacc[j][1] > -1e29f) ? ex2f((sacc[j][1] - mx0) * LOG2E) : 0.f;
            float p2 = (sacc[j][2] > -1e29f) ? ex2f((sacc[j][2] - mx1) * LOG2E) : 0.f;
            float p3 = (sacc[j][3] > -1e29f) ? ex2f((sacc[j][3] - mx1) * LOG2E) : 0.f;
            sacc[j][0] = p0; sacc[j][1] = p1; sacc[j][2] = p2; sacc[j][3] = p3;
            la0 += p0 + p1;
            la1 += p2 + p3;
        }
        la0 += __shfl_xor_sync(0xffffffffu, la0, 1);
        la0 += __shfl_xor_sync(0xffffffffu, la0, 2);
        la1 += __shfl_xor_sync(0xffffffffu, la1, 1);
        la1 += __shfl_xor_sync(0xffffffffu, la1, 2);
        l0 = l0 * sc0 + la0;
        l1 = l1 * sc1 + la1;
        m0 = mx0; m1 = mx1;

#pragma unroll
        for (int nf = 0; nf < 16; nf++) {
            oacc[nf][0] *= sc0; oacc[nf][1] *= sc0;
            oacc[nf][2] *= sc1; oacc[nf][3] *= sc1;
        }

#pragma unroll
        for (int s4 = 0; s4 < 4; s4++) {
            uint32_t ah[4], al[4];
            pack_hilo(sacc[2 * s4][0],     sacc[2 * s4][1],     ah[0], al[0]);
            pack_hilo(sacc[2 * s4][2],     sacc[2 * s4][3],     ah[1], al[1]);
            pack_hilo(sacc[2 * s4 + 1][0], sacc[2 * s4 + 1][1], ah[2], al[2]);
            pack_hilo(sacc[2 * s4 + 1][2], sacc[2 * s4 + 1][3], ah[3], al[3]);

            const uint32_t vbase = stb + 2 * AMAT * 2 + vrow_off +
                                   (uint32_t)(s4 * 16 * AT_PAD) * 2;
#pragma unroll
            for (int db = 0; db < 8; db++) {
                uint32_t vh[4], vl[4];
                const uint32_t voff = vbase + db * 32;
                ldsm4t(vh, voff);
                ldsm4t(vl, voff + AMAT * 2);
                mma16816(oacc[2 * db],     ah, vh);
                mma16816(oacc[2 * db],     ah, vl);
                mma16816(oacc[2 * db],     al, vh);
                mma16816(oacc[2 * db + 1], ah, &vh[2]);
                mma16816(oacc[2 * db + 1], ah, &vl[2]);
                mma16816(oacc[2 * db + 1], al, &vh[2]);
            }
        }
        __syncthreads();
    }
#undef LOAD_KV

    const float inv0 = 1.f / l0;
    const float inv1 = 1.f / l1;
    const size_t o0 = (size_t)(b * S_ + qg0) * (NH_ * D_) + h * D_;
    const size_t o1 = (size_t)(b * S_ + qg1) * (NH_ * D_) + h * D_;
#pragma unroll
    for (int nf = 0; nf < 16; nf++) {
        const int dc = 8 * nf + 2 * (lane & 3);
        uint32_t hw, lw;
        pack_hilo(oacc[nf][0] * inv0, oacc[nf][1] * inv0, hw, lw);
        *(uint32_t*)(g_at_hi + o0 + dc) = hw;
        *(uint32_t*)(g_at_lo + o0 + dc) = lw;
        pack_hilo(oacc[nf][2] * inv1, oacc[nf][3] * inv1, hw, lw);
        *(uint32_t*)(g_at_hi + o1 + dc) = hw;
        *(uint32_t*)(g_at_lo + o1 + dc) = lw;
    }
}

/* --------------------------------- launch --------------------------------- */
extern "C" void kernel_launch(void* const* d_in, const int* in_sizes, int n_in,
                              void* d_out, int out_size)
{
    const float* hidden = (const float*)d_in[0];
    const float* cosp   = (const float*)d_in[1];
    const float* sinp   = (const float*)d_in[2];
    const float* w_qkv  = (const float*)d_in[3];
    const float* b_qkv  = (const float*)d_in[4];
    const float* w_o    = (const float*)d_in[5];
    const float* b_o    = (const float*)d_in[6];
    float* out = (float*)d_out;

    __nv_bfloat16 *p_h_hi, *p_h_lo, *p_wq_hi, *p_wq_lo, *p_wo_hi, *p_wo_lo,
                  *p_at_hi, *p_at_lo;
    cudaGetSymbolAddress((void**)&p_h_hi, g_h_hi);
    cudaGetSymbolAddress((void**)&p_h_lo, g_h_lo);
    cudaGetSymbolAddress((void**)&p_wq_hi, g_wq_hi);
    cudaGetSymbolAddress((void**)&p_wq_lo, g_wq_lo);
    cudaGetSymbolAddress((void**)&p_wo_hi, g_wo_hi);
    cudaGetSymbolAddress((void**)&p_wo_lo, g_wo_lo);
    cudaGetSymbolAddress((void**)&p_at_hi, g_at_hi);
    cudaGetSymbolAddress((void**)&p_at_lo, g_at_lo);

    cudaFuncSetAttribute(gemm_mma_bf16x3,
                         cudaFuncAttributeMaxDynamicSharedMemorySize, GSMEM);
    cudaFuncSetAttribute(attn_mma,
                         cudaFuncAttributeMaxDynamicSharedMemorySize, ATTN_SMEM_B);

    /* converts */
    cvt_split<<<(BS_ * HID_ / 4 + 255) / 256, 256>>>(hidden, p_h_hi, p_h_lo,
                                                     BS_ * HID_ / 4);
    cvt_split<<<(QKV_OUT_ * HID_ / 4 + 255) / 256, 256>>>(w_qkv, p_wq_hi, p_wq_lo,
                                                          QKV_OUT_ * HID_ / 4);
    cvt_split<<<(HID_ * HID_ / 4 + 255) / 256, 256>>>(w_o, p_wo_hi, p_wo_lo,
                                                      HID_ * HID_ / 4);

    /* 1) qkv GEMM with fused RoPE/split epilogue (mode 1) */
    gemm_mma_bf16x3<<<dim3(QKV_OUT_ / 256, BS_ / 128), 512, GSMEM>>>(
        p_h_hi, p_h_lo, p_wq_hi, p_wq_lo, b_qkv, nullptr,
        cosp, sinp, QKV_OUT_, HID_, 1);

    /* 2) HMMA flash attention (writes bf16 hi/lo directly) */
    attn_mma<<<dim3(S_ / 128, NH_, B_), 256, ATTN_SMEM_B>>>();

    /* 3) out = attn @ w_o^T + b_o (mode 0) */
    gemm_mma_bf16x3<<<dim3(HID_ / 256, BS_ / 128), 512, GSMEM>>>(
        p_at_hi, p_at_lo, p_wo_hi, p_wo_lo, b_o, out,
        nullptr, nullptr, HID_, HID_, 0);
}